// round 1
// baseline (speedup 1.0000x reference)
#include <cuda_runtime.h>
#include <cuda_bf16.h>

// ---------------------------------------------------------------------------
// GCN forward: B=64, N=1024, NFEAT=512, NHID1=1024, NHID2=512
//   support1 = X2d[65536,512] @ W1[512,1024]                  (GEMM1)
//   h1       = relu(adj[b] @ support1[b] + b1)   64x(1024,1024,1024)  (GEMM2)
//   support2 = H1_2d[65536,1024] @ W2[1024,512]               (GEMM3)
//   h2       = relu(adj[b] @ support2[b] + b2)   64x(1024,512,1024)   (GEMM4)
//   out[b]   = (1/len) * sum_{n<len,h} h2[b,n,h]*Wl[h] + bl   (POOL)
// ---------------------------------------------------------------------------

#define BM 128
#define BN 128
#define BK 16
#define TM 8
#define TN 8

// Scratch: ping-pong buffers (256 MB each). Static device arrays — no allocs.
__device__ float g_buf1[64u * 1024u * 1024u];  // support1 / support2
__device__ float g_buf2[64u * 1024u * 1024u];  // h1 / h2

template <bool RELU>
__global__ void __launch_bounds__(256)
gemm_kernel(const float* __restrict__ Ag, const float* __restrict__ Bg,
            const float* __restrict__ bias, float* __restrict__ Cg,
            int M, int N, int K,
            size_t sA, size_t sB, size_t sC)
{
    const float* A = Ag + (size_t)blockIdx.z * sA;
    const float* B = Bg + (size_t)blockIdx.z * sB;
    float*       C = Cg + (size_t)blockIdx.z * sC;

    __shared__ float As[2][BK][BM + 4];
    __shared__ float Bs[2][BK][BN];

    const int tid = threadIdx.x;
    const int tx = tid & 15;      // 0..15  -> N direction (TN=8)
    const int ty = tid >> 4;      // 0..15  -> M direction (TM=8)

    const int m0 = blockIdx.y * BM;
    const int n0 = blockIdx.x * BN;

    // Staging index math (2 float4 per thread for each of A and B tiles)
    const int a_m0 = tid >> 2;            // 0..63
    const int a_m1 = (tid + 256) >> 2;    // 64..127
    const int a_k4 = (tid & 3) * 4;       // 0,4,8,12
    const int b_k0 = tid >> 5;            // 0..7
    const int b_k1 = (tid + 256) >> 5;    // 8..15
    const int b_n  = (tid & 31) * 4;      // 0..124

    float4 ra0, ra1, rb0, rb1;

    // fetch tile kt into registers
    #define FETCH(kt)                                                            \
        do {                                                                     \
            ra0 = *(const float4*)(A + (size_t)(m0 + a_m0) * K + (kt) * BK + a_k4); \
            ra1 = *(const float4*)(A + (size_t)(m0 + a_m1) * K + (kt) * BK + a_k4); \
            rb0 = *(const float4*)(B + (size_t)((kt) * BK + b_k0) * N + n0 + b_n);  \
            rb1 = *(const float4*)(B + (size_t)((kt) * BK + b_k1) * N + n0 + b_n);  \
        } while (0)

    #define STORE(buf)                                                           \
        do {                                                                     \
            As[buf][a_k4 + 0][a_m0] = ra0.x;                                     \
            As[buf][a_k4 + 1][a_m0] = ra0.y;                                     \
            As[buf][a_k4 + 2][a_m0] = ra0.z;                                     \
            As[buf][a_k4 + 3][a_m0] = ra0.w;                                     \
            As[buf][a_k4 + 0][a_m1] = ra1.x;                                     \
            As[buf][a_k4 + 1][a_m1] = ra1.y;                                     \
            As[buf][a_k4 + 2][a_m1] = ra1.z;                                     \
            As[buf][a_k4 + 3][a_m1] = ra1.w;                                     \
            *(float4*)(&Bs[buf][b_k0][b_n]) = rb0;                               \
            *(float4*)(&Bs[buf][b_k1][b_n]) = rb1;                               \
        } while (0)

    float acc[TM][TN] = {};

    FETCH(0);
    STORE(0);
    __syncthreads();

    const int nk = K / BK;
    for (int kt = 0; kt < nk; kt++) {
        const int cur = kt & 1;
        if (kt + 1 < nk) FETCH(kt + 1);

        #pragma unroll
        for (int k = 0; k < BK; k++) {
            float4 a0 = *(const float4*)(&As[cur][k][ty * TM]);
            float4 a1 = *(const float4*)(&As[cur][k][ty * TM + 4]);
            float4 b0 = *(const float4*)(&Bs[cur][k][tx * TN]);
            float4 b1 = *(const float4*)(&Bs[cur][k][tx * TN + 4]);
            float ra[TM] = {a0.x, a0.y, a0.z, a0.w, a1.x, a1.y, a1.z, a1.w};
            float rb[TN] = {b0.x, b0.y, b0.z, b0.w, b1.x, b1.y, b1.z, b1.w};
            #pragma unroll
            for (int i = 0; i < TM; i++)
                #pragma unroll
                for (int j = 0; j < TN; j++)
                    acc[i][j] = fmaf(ra[i], rb[j], acc[i][j]);
        }

        if (kt + 1 < nk) STORE(cur ^ 1);
        __syncthreads();
    }

    // Epilogue: optional bias (indexed by N/hidden dim) + ReLU, vectorized stores
    float rbias[TN];
    #pragma unroll
    for (int j = 0; j < TN; j++) rbias[j] = 0.0f;
    if (bias != nullptr) {
        const float* bp = bias + n0 + tx * TN;
        #pragma unroll
        for (int j = 0; j < TN; j++) rbias[j] = bp[j];
    }

    #pragma unroll
    for (int i = 0; i < TM; i++) {
        const int row = m0 + ty * TM + i;
        float* crow = C + (size_t)row * N + n0 + tx * TN;
        #pragma unroll
        for (int j4 = 0; j4 < TN; j4 += 4) {
            float4 v;
            float v0 = acc[i][j4 + 0] + rbias[j4 + 0];
            float v1 = acc[i][j4 + 1] + rbias[j4 + 1];
            float v2 = acc[i][j4 + 2] + rbias[j4 + 2];
            float v3 = acc[i][j4 + 3] + rbias[j4 + 3];
            if (RELU) {
                v0 = fmaxf(v0, 0.0f);
                v1 = fmaxf(v1, 0.0f);
                v2 = fmaxf(v2, 0.0f);
                v3 = fmaxf(v3, 0.0f);
            }
            v.x = v0; v.y = v1; v.z = v2; v.w = v3;
            *(float4*)(crow + j4) = v;
        }
    }
    #undef FETCH
    #undef STORE
}

// Fused masked mean-pool + final linear: out[b] = (1/len) * sum h2[b,n,h]*Wl[h] + bl
__global__ void __launch_bounds__(256)
pool_kernel(const float* __restrict__ h2, const float* __restrict__ Wl,
            const float* __restrict__ bl, const int* __restrict__ length,
            float* __restrict__ out)
{
    __shared__ float sW[512];
    __shared__ float red[256];

    const int b = blockIdx.x;
    const int tid = threadIdx.x;

    for (int i = tid; i < 512; i += 256) sW[i] = Wl[i];
    __syncthreads();

    const int len = length[b];
    const float* base = h2 + (size_t)b * 1024 * 512;
    const int total = len * 512;

    float acc = 0.0f;
    // float4 over the contiguous [len*512] range; 512 | total so total%4==0
    const float4* base4 = (const float4*)base;
    const int total4 = total >> 2;
    for (int i4 = tid; i4 < total4; i4 += 256) {
        float4 v = base4[i4];
        const int h = (i4 << 2) & 511;
        acc = fmaf(v.x, sW[h + 0], acc);
        acc = fmaf(v.y, sW[h + 1], acc);
        acc = fmaf(v.z, sW[h + 2], acc);
        acc = fmaf(v.w, sW[h + 3], acc);
    }

    red[tid] = acc;
    __syncthreads();
    #pragma unroll
    for (int s = 128; s > 0; s >>= 1) {
        if (tid < s) red[tid] += red[tid + s];
        __syncthreads();
    }
    if (tid == 0) out[b] = red[0] / (float)len + bl[0];
}

extern "C" void kernel_launch(void* const* d_in, const int* in_sizes, int n_in,
                              void* d_out, int out_size)
{
    const float* x      = (const float*)d_in[0];  // [64,1024,512]
    const float* adj    = (const float*)d_in[1];  // [64,1024,1024]
    const int*   length = (const int*)  d_in[2];  // [64]
    const float* W1     = (const float*)d_in[3];  // [512,1024]
    const float* b1     = (const float*)d_in[4];  // [1024]
    const float* W2     = (const float*)d_in[5];  // [1024,512]
    const float* b2     = (const float*)d_in[6];  // [512]
    const float* Wl     = (const float*)d_in[7];  // [512,1]
    const float* bl     = (const float*)d_in[8];  // [1]
    float* out = (float*)d_out;                   // [64,1]

    float *buf1, *buf2;
    cudaGetSymbolAddress((void**)&buf1, g_buf1);
    cudaGetSymbolAddress((void**)&buf2, g_buf2);

    const int B = 64, N = 1024, NFEAT = 512, NHID1 = 1024, NHID2 = 512;

    // GEMM1: support1[65536,1024] = X2d[65536,512] @ W1[512,1024]
    {
        dim3 grid(NHID1 / BN, (B * N) / BM, 1);
        gemm_kernel<false><<<grid, 256>>>(x, W1, nullptr, buf1,
                                          B * N, NHID1, NFEAT, 0, 0, 0);
    }
    // GEMM2: h1[b] = relu(adj[b] @ support1[b] + b1), 64 batches of 1024x1024x1024
    {
        dim3 grid(NHID1 / BN, N / BM, B);
        gemm_kernel<true><<<grid, 256>>>(adj, buf1, b1, buf2,
                                         N, NHID1, N,
                                         (size_t)N * N, (size_t)N * NHID1, (size_t)N * NHID1);
    }
    // GEMM3: support2[65536,512] = H1_2d[65536,1024] @ W2[1024,512]
    {
        dim3 grid(NHID2 / BN, (B * N) / BM, 1);
        gemm_kernel<false><<<grid, 256>>>(buf2, W2, nullptr, buf1,
                                          B * N, NHID2, NHID1, 0, 0, 0);
    }
    // GEMM4: h2[b] = relu(adj[b] @ support2[b] + b2), 64 batches of 1024x512x1024
    {
        dim3 grid(NHID2 / BN, N / BM, B);
        gemm_kernel<true><<<grid, 256>>>(adj, buf1, b2, buf2,
                                         N, NHID2, N,
                                         (size_t)N * N, (size_t)N * NHID2, (size_t)N * NHID2);
    }
    // POOL + final linear
    pool_kernel<<<B, 256>>>(buf2, Wl, bl, length, out);

    (void)in_sizes; (void)n_in; (void)out_size;
}

// round 3
// speedup vs baseline: 3.2341x; 3.2341x over previous
#include <cuda_runtime.h>
#include <cuda_bf16.h>
#include <stdint.h>

// ===========================================================================
// GCN forward via mma.sync bf16 hi/lo-split GEMMs (fp32 accumulate).
//   B=64, N=1024, NFEAT=512, NHID1=1024, NHID2=512
//   G1: support1^T[1024,65536]  = W1^T[1024,512] @ X^T       (K=512)
//   G2: h1[b][1024,1024]        = relu(adj[b] @ support1[b] + b1)  (K=1024)
//   G3: support2^T[512,65536]   = W2^T[512,1024] @ h1^T      (K=1024)
//   G4: h2[b][1024,512]         = relu(adj[b] @ support2[b] + b2)  (K=1024)
//   pool: out[b] = mean_{n<len} h2[b,n,:] . Wl + bl
// All MMA operands are K-major row lists (A rows of K, B n-rows of K),
// SW128-swizzled in SMEM, loaded via cp.async, consumed via ldmatrix.
// ===========================================================================

#define BM 128
#define BN 128
#define BK 64                      // bf16 per chunk (= 128 bytes per row)

#define A_HI 0
#define A_LO (16 * 1024)
#define B_HI (32 * 1024)
#define B_LO (48 * 1024)
#define STG  (64 * 1024)
#define SMEM_TOTAL (2 * STG)       // 131072

#define SWZ(off) ((off) ^ (((off) >> 3) & 0x70))

__device__ __forceinline__ uint32_t smem_u32(const void* p) {
    uint32_t a;
    asm("{ .reg .u64 t; cvta.to.shared.u64 t, %1; cvt.u32.u64 %0, t; }" : "=r"(a) : "l"(p));
    return a;
}
__device__ __forceinline__ void cp16(uint32_t dst, const void* src) {
    asm volatile("cp.async.cg.shared.global [%0], [%1], 16;" :: "r"(dst), "l"(src));
}
#define CP_COMMIT() asm volatile("cp.async.commit_group;" ::: "memory")
#define CP_WAIT(n)  asm volatile("cp.async.wait_group %0;" :: "n"(n) : "memory")

__device__ __forceinline__ void ldsm4(uint32_t* r, uint32_t addr) {
    asm volatile("ldmatrix.sync.aligned.m8n8.x4.shared.b16 {%0,%1,%2,%3}, [%4];"
                 : "=r"(r[0]), "=r"(r[1]), "=r"(r[2]), "=r"(r[3]) : "r"(addr));
}
__device__ __forceinline__ void mma_bf16(float* d, const uint32_t* a, const uint32_t* b) {
    asm volatile("mma.sync.aligned.m16n8k16.row.col.f32.bf16.bf16.f32 "
                 "{%0,%1,%2,%3}, {%4,%5,%6,%7}, {%8,%9}, {%0,%1,%2,%3};"
                 : "+f"(d[0]), "+f"(d[1]), "+f"(d[2]), "+f"(d[3])
                 : "r"(a[0]), "r"(a[1]), "r"(a[2]), "r"(a[3]), "r"(b[0]), "r"(b[1]));
}
__device__ __forceinline__ uint32_t pack2bf(float a, float b) {
    __nv_bfloat162 t = __floats2bfloat162_rn(a, b);
    return *(uint32_t*)&t;
}

// ---------------------------------------------------------------------------
// Static device scratch (no allocations)
// ---------------------------------------------------------------------------
__device__ __nv_bfloat16 g_Xhi[64u * 1024u * 512u],  g_Xlo[64u * 1024u * 512u];
__device__ __nv_bfloat16 g_Jhi[64u * 1024u * 1024u], g_Jlo[64u * 1024u * 1024u];
__device__ __nv_bfloat16 g_W1hi[1024u * 512u],  g_W1lo[1024u * 512u];   // W1^T
__device__ __nv_bfloat16 g_W2hi[512u * 1024u],  g_W2lo[512u * 1024u];   // W2^T
__device__ __nv_bfloat16 g_S1hi[1024u * 65536u], g_S1lo[1024u * 65536u]; // support1^T
__device__ __nv_bfloat16 g_H1hi[65536u * 1024u], g_H1lo[65536u * 1024u]; // h1
__device__ __nv_bfloat16 g_S2hi[512u * 65536u],  g_S2lo[512u * 65536u];  // support2^T
__device__ float         g_H2[65536u * 512u];                            // h2 fp32

// ---------------------------------------------------------------------------
// fp32 -> bf16 hi/lo split
// ---------------------------------------------------------------------------
__global__ void __launch_bounds__(256)
split_kernel(const float* __restrict__ src, __nv_bfloat16* __restrict__ hi,
             __nv_bfloat16* __restrict__ lo, size_t n4)
{
    size_t stride = (size_t)gridDim.x * blockDim.x;
    for (size_t i = (size_t)blockIdx.x * blockDim.x + threadIdx.x; i < n4; i += stride) {
        float4 v = ((const float4*)src)[i];
        __nv_bfloat16 h0 = __float2bfloat16(v.x), h1 = __float2bfloat16(v.y);
        __nv_bfloat16 h2 = __float2bfloat16(v.z), h3 = __float2bfloat16(v.w);
        uint2 ho, lv;
        ho.x = pack2bf(v.x, v.y);
        ho.y = pack2bf(v.z, v.w);
        lv.x = pack2bf(v.x - __bfloat162float(h0), v.y - __bfloat162float(h1));
        lv.y = pack2bf(v.z - __bfloat162float(h2), v.w - __bfloat162float(h3));
        ((uint2*)hi)[i] = ho;
        ((uint2*)lo)[i] = lv;
    }
}

__global__ void __launch_bounds__(256)
tsplit_kernel(const float* __restrict__ src, __nv_bfloat16* __restrict__ hi,
              __nv_bfloat16* __restrict__ lo, int R, int C)
{
    int total = R * C;
    for (int idx = blockIdx.x * blockDim.x + threadIdx.x; idx < total;
         idx += gridDim.x * blockDim.x) {
        int r = idx / C, c = idx % C;
        float v = src[idx];
        __nv_bfloat16 h = __float2bfloat16(v);
        hi[(size_t)c * R + r] = h;
        lo[(size_t)c * R + r] = __float2bfloat16(v - __bfloat162float(h));
    }
}

// ---------------------------------------------------------------------------
// mma.sync GEMM: D[BM,BN] per CTA, 8 warps (2x4), warp tile 64x32.
// EPI: 0 = split-bf16 out; 1 = bias+ReLU, split-bf16 out; 2 = bias+ReLU, fp32.
// ---------------------------------------------------------------------------
template <int EPI>
__global__ void __launch_bounds__(256)
mma_gemm(const __nv_bfloat16* __restrict__ Ahi, const __nv_bfloat16* __restrict__ Alo,
         int lda, size_t strA,
         const __nv_bfloat16* __restrict__ Bhi, const __nv_bfloat16* __restrict__ Blo,
         int ldb, size_t strB,
         const float* __restrict__ bias,
         __nv_bfloat16* __restrict__ Chi, __nv_bfloat16* __restrict__ Clo,
         float* __restrict__ Cf, int ldc, size_t strC,
         int nch)
{
    extern __shared__ char smem[];
    const uint32_t sb = smem_u32(smem);
    const int tid = threadIdx.x;
    const int wid = tid >> 5;
    const int l   = tid & 31;
    const int warp_m = wid & 1;    // 0..1 -> 64 rows each
    const int warp_n = wid >> 1;   // 0..3 -> 32 cols each
    const int bz = blockIdx.z;
    const int m0 = blockIdx.y * BM;
    const int n0 = blockIdx.x * BN;

    const __nv_bfloat16* pAhi = Ahi + strA * bz;
    const __nv_bfloat16* pAlo = Alo + strA * bz;
    const __nv_bfloat16* pBhi = Bhi + strB * bz;
    const __nv_bfloat16* pBlo = Blo + strB * bz;

    // per-thread cp.async slots: 4 per tile (A/B x hi/lo = 16 total per chunk)
    const int ld_row = tid >> 3;        // 0..31, +32*it
    const int ld_c16 = tid & 7;         // 16B column

    auto load_tiles = [&](int c, int st) {
        const int kbase = c * BK;
        const uint32_t sbase = sb + st * STG;
        #pragma unroll
        for (int it = 0; it < 4; it++) {
            const int row = ld_row + it * 32;
            const uint32_t sw = SWZ((uint32_t)(row * 128 + ld_c16 * 16));
            const size_t ga = (size_t)(m0 + row) * lda + kbase + ld_c16 * 8;
            cp16(sbase + A_HI + sw, pAhi + ga);
            cp16(sbase + A_LO + sw, pAlo + ga);
            const size_t gb = (size_t)(n0 + row) * ldb + kbase + ld_c16 * 8;
            cp16(sbase + B_HI + sw, pBhi + gb);
            cp16(sbase + B_LO + sw, pBlo + gb);
        }
    };

    // ldmatrix per-lane geometry
    const int a_row_l  = l & 15;               // row within 16
    const uint32_t a_koff = (uint32_t)((l >> 4) * 16);          // bytes
    const int b_row_l  = (l & 7) + ((l >> 4) * 8);              // n within 16
    const uint32_t b_koff = (uint32_t)(((l >> 3) & 1) * 16);    // bytes

    uint32_t a_rb[4], b_rb[2];
    #pragma unroll
    for (int mi = 0; mi < 4; mi++)
        a_rb[mi] = (uint32_t)((warp_m * 64 + mi * 16 + a_row_l) * 128);
    #pragma unroll
    for (int nb = 0; nb < 2; nb++)
        b_rb[nb] = (uint32_t)((warp_n * 32 + nb * 16 + b_row_l) * 128);

    float acc[4][4][4];
    #pragma unroll
    for (int mi = 0; mi < 4; mi++)
        #pragma unroll
        for (int ni = 0; ni < 4; ni++)
            #pragma unroll
            for (int q = 0; q < 4; q++) acc[mi][ni][q] = 0.0f;

    load_tiles(0, 0);
    CP_COMMIT();

    for (int c = 0; c < nch; c++) {
        const int cur = c & 1;
        if (c + 1 < nch) {
            load_tiles(c + 1, cur ^ 1);
            CP_COMMIT();
            CP_WAIT(1);
        } else {
            CP_WAIT(0);
        }
        __syncthreads();

        const uint32_t sAh = sb + cur * STG + A_HI;
        const uint32_t sAl = sb + cur * STG + A_LO;
        const uint32_t sBh = sb + cur * STG + B_HI;
        const uint32_t sBl = sb + cur * STG + B_LO;

        #pragma unroll
        for (int ks = 0; ks < 4; ks++) {
            const uint32_t kb = (uint32_t)(ks * 32);
            uint32_t Ah[4][4], Al[4][4], Bh[2][4], Bl[2][4];
            #pragma unroll
            for (int mi = 0; mi < 4; mi++) {
                const uint32_t off = SWZ(a_rb[mi] + kb + a_koff);
                ldsm4(Ah[mi], sAh + off);
                ldsm4(Al[mi], sAl + off);
            }
            #pragma unroll
            for (int nb = 0; nb < 2; nb++) {
                const uint32_t off = SWZ(b_rb[nb] + kb + b_koff);
                ldsm4(Bh[nb], sBh + off);
                ldsm4(Bl[nb], sBl + off);
            }
            #pragma unroll
            for (int mi = 0; mi < 4; mi++) {
                #pragma unroll
                for (int ni = 0; ni < 4; ni++) {
                    const uint32_t* bh = &Bh[ni >> 1][(ni & 1) * 2];
                    const uint32_t* bl = &Bl[ni >> 1][(ni & 1) * 2];
                    mma_bf16(acc[mi][ni], Ah[mi], bh);
                    mma_bf16(acc[mi][ni], Ah[mi], bl);
                    mma_bf16(acc[mi][ni], Al[mi], bh);
                }
            }
        }
        __syncthreads();
    }

    // ---- epilogue ----
    const int er = warp_m * 64 + (l >> 2);         // + mi*16, and +8 variant
    const int ec = warp_n * 32 + 2 * (l & 3);      // + ni*8
    #pragma unroll
    for (int mi = 0; mi < 4; mi++) {
        const int row = m0 + er + mi * 16;
        const size_t ro0 = strC * bz + (size_t)row * ldc;
        const size_t ro1 = ro0 + (size_t)8 * ldc;
        #pragma unroll
        for (int ni = 0; ni < 4; ni++) {
            const int col = n0 + ec + ni * 8;
            float v00 = acc[mi][ni][0], v01 = acc[mi][ni][1];
            float v10 = acc[mi][ni][2], v11 = acc[mi][ni][3];
            if (EPI >= 1) {
                const float2 bb = *(const float2*)(bias + col);
                v00 = fmaxf(v00 + bb.x, 0.0f);
                v01 = fmaxf(v01 + bb.y, 0.0f);
                v10 = fmaxf(v10 + bb.x, 0.0f);
                v11 = fmaxf(v11 + bb.y, 0.0f);
            }
            if (EPI <= 1) {
                const uint32_t h0 = pack2bf(v00, v01);
                const uint32_t h1 = pack2bf(v10, v11);
                float l00 = v00 - __bfloat162float(__float2bfloat16(v00));
                float l01 = v01 - __bfloat162float(__float2bfloat16(v01));
                float l10 = v10 - __bfloat162float(__float2bfloat16(v10));
                float l11 = v11 - __bfloat162float(__float2bfloat16(v11));
                *(uint32_t*)(Chi + ro0 + col) = h0;
                *(uint32_t*)(Chi + ro1 + col) = h1;
                *(uint32_t*)(Clo + ro0 + col) = pack2bf(l00, l01);
                *(uint32_t*)(Clo + ro1 + col) = pack2bf(l10, l11);
            } else {
                *(float2*)(Cf + ro0 + col) = make_float2(v00, v01);
                *(float2*)(Cf + ro1 + col) = make_float2(v10, v11);
            }
        }
    }
}

// ---------------------------------------------------------------------------
// pool: out[b] = mean_{n<len} h2[b,n,:] . Wl + bl
// ---------------------------------------------------------------------------
__global__ void __launch_bounds__(256)
pool_kernel(const float* __restrict__ h2, const float* __restrict__ Wl,
            const float* __restrict__ bl, const int* __restrict__ length,
            float* __restrict__ out)
{
    __shared__ float sW[512];
    __shared__ float red[256];
    const int b = blockIdx.x;
    const int tid = threadIdx.x;
    for (int i = tid; i < 512; i += 256) sW[i] = Wl[i];
    __syncthreads();
    const int len = length[b];
    const float4* base4 = (const float4*)(h2 + (size_t)b * 1024 * 512);
    const int total4 = (len * 512) >> 2;
    float acc = 0.0f;
    for (int i4 = tid; i4 < total4; i4 += 256) {
        float4 v = base4[i4];
        const int h = (i4 << 2) & 511;
        acc = fmaf(v.x, sW[h + 0], acc);
        acc = fmaf(v.y, sW[h + 1], acc);
        acc = fmaf(v.z, sW[h + 2], acc);
        acc = fmaf(v.w, sW[h + 3], acc);
    }
    red[tid] = acc;
    __syncthreads();
    #pragma unroll
    for (int s = 128; s > 0; s >>= 1) {
        if (tid < s) red[tid] += red[tid + s];
        __syncthreads();
    }
    if (tid == 0) out[b] = red[0] / (float)len + bl[0];
}

// ---------------------------------------------------------------------------
extern "C" void kernel_launch(void* const* d_in, const int* in_sizes, int n_in,
                              void* d_out, int out_size)
{
    const float* x      = (const float*)d_in[0];
    const float* adj    = (const float*)d_in[1];
    const int*   length = (const int*)  d_in[2];
    const float* W1     = (const float*)d_in[3];
    const float* b1     = (const float*)d_in[4];
    const float* W2     = (const float*)d_in[5];
    const float* b2     = (const float*)d_in[6];
    const float* Wl     = (const float*)d_in[7];
    const float* bl     = (const float*)d_in[8];
    float* out = (float*)d_out;

    __nv_bfloat16 *Xhi, *Xlo, *Jhi, *Jlo, *W1hi, *W1lo, *W2hi, *W2lo;
    __nv_bfloat16 *S1hi, *S1lo, *H1hi, *H1lo, *S2hi, *S2lo;
    float* H2;
    cudaGetSymbolAddress((void**)&Xhi, g_Xhi);   cudaGetSymbolAddress((void**)&Xlo, g_Xlo);
    cudaGetSymbolAddress((void**)&Jhi, g_Jhi);   cudaGetSymbolAddress((void**)&Jlo, g_Jlo);
    cudaGetSymbolAddress((void**)&W1hi, g_W1hi); cudaGetSymbolAddress((void**)&W1lo, g_W1lo);
    cudaGetSymbolAddress((void**)&W2hi, g_W2hi); cudaGetSymbolAddress((void**)&W2lo, g_W2lo);
    cudaGetSymbolAddress((void**)&S1hi, g_S1hi); cudaGetSymbolAddress((void**)&S1lo, g_S1lo);
    cudaGetSymbolAddress((void**)&H1hi, g_H1hi); cudaGetSymbolAddress((void**)&H1lo, g_H1lo);
    cudaGetSymbolAddress((void**)&S2hi, g_S2hi); cudaGetSymbolAddress((void**)&S2lo, g_S2lo);
    cudaGetSymbolAddress((void**)&H2, g_H2);

    cudaFuncSetAttribute(mma_gemm<0>, cudaFuncAttributeMaxDynamicSharedMemorySize, SMEM_TOTAL);
    cudaFuncSetAttribute(mma_gemm<1>, cudaFuncAttributeMaxDynamicSharedMemorySize, SMEM_TOTAL);
    cudaFuncSetAttribute(mma_gemm<2>, cudaFuncAttributeMaxDynamicSharedMemorySize, SMEM_TOTAL);

    // conversions
    split_kernel<<<4096, 256>>>(x,   Xhi, Xlo, (size_t)64 * 1024 * 512 / 4);
    split_kernel<<<4096, 256>>>(adj, Jhi, Jlo, (size_t)64 * 1024 * 1024 / 4);
    tsplit_kernel<<<512, 256>>>(W1, W1hi, W1lo, 512, 1024);
    tsplit_kernel<<<512, 256>>>(W2, W2hi, W2lo, 1024, 512);

    // G1: support1^T[1024,65536] = W1^T @ X^T  (M=1024, N=65536, K=512)
    mma_gemm<0><<<dim3(512, 8, 1), 256, SMEM_TOTAL>>>(
        W1hi, W1lo, 512, 0, Xhi, Xlo, 512, 0, nullptr,
        S1hi, S1lo, nullptr, 65536, 0, 512 / BK);

    // G2: h1[b] = relu(adj[b] @ support1[b] + b1)  (M=1024, N=1024, K=1024) x64
    mma_gemm<1><<<dim3(8, 8, 64), 256, SMEM_TOTAL>>>(
        Jhi, Jlo, 1024, (size_t)1024 * 1024,
        S1hi, S1lo, 65536, 1024, b1,
        H1hi, H1lo, nullptr, 1024, (size_t)1024 * 1024, 1024 / BK);

    // G3: support2^T[512,65536] = W2^T @ h1^T  (M=512, N=65536, K=1024)
    mma_gemm<0><<<dim3(512, 4, 1), 256, SMEM_TOTAL>>>(
        W2hi, W2lo, 1024, 0, H1hi, H1lo, 1024, 0, nullptr,
        S2hi, S2lo, nullptr, 65536, 0, 1024 / BK);

    // G4: h2[b] = relu(adj[b] @ support2[b] + b2)  (M=1024, N=512, K=1024) x64
    mma_gemm<2><<<dim3(4, 8, 64), 256, SMEM_TOTAL>>>(
        Jhi, Jlo, 1024, (size_t)1024 * 1024,
        S2hi, S2lo, 65536, 1024, b2,
        nullptr, nullptr, H2, 512, (size_t)1024 * 512, 1024 / BK);

    pool_kernel<<<64, 256>>>(H2, Wl, bl, length, out);

    (void)in_sizes; (void)n_in; (void)out_size;
}

// round 4
// speedup vs baseline: 5.2790x; 1.6323x over previous
#include <cuda_runtime.h>
#include <cuda_fp16.h>
#include <stdint.h>

// ===========================================================================
// GCN forward via single-pass fp16 mma.sync GEMMs (fp32 accumulate).
//   B=64, N=1024, NFEAT=512, NHID1=1024, NHID2=512
//   G1: support1^T[1024,65536]  = W1^T[1024,512] @ X^T       (K=512)
//   G2: h1[b][1024,1024]        = relu(adj[b] @ support1[b] + b1)  (K=1024)
//   G3: support2^T[512,65536]   = W2^T[512,1024] @ h1^T      (K=1024)
//   G4: h2[b][1024,512]         = relu(adj[b] @ support2[b] + b2)  (K=1024)
//   pool: out[b] = mean_{n<len} h2[b,n,:] . Wl + bl
// All MMA operands are K-major fp16 rows, SW128-swizzled in SMEM via
// cp.async (3-stage pipeline), consumed via ldmatrix.
// ===========================================================================

#define BM 128
#define BN 256
#define BK 64                       // fp16 per chunk (=128 bytes per row)
#define NSTG 3

#define A_BYTES (BM * 128)          // 16384
#define B_BYTES (BN * 128)          // 32768
#define STG     (A_BYTES + B_BYTES) // 49152
#define SMEM_TOTAL (NSTG * STG)     // 147456

#define SWZ(off) ((off) ^ (((off) >> 3) & 0x70))

__device__ __forceinline__ uint32_t smem_u32(const void* p) {
    uint32_t a;
    asm("{ .reg .u64 t; cvta.to.shared.u64 t, %1; cvt.u32.u64 %0, t; }" : "=r"(a) : "l"(p));
    return a;
}
__device__ __forceinline__ void cp16(uint32_t dst, const void* src) {
    asm volatile("cp.async.cg.shared.global [%0], [%1], 16;" :: "r"(dst), "l"(src));
}
#define CP_COMMIT() asm volatile("cp.async.commit_group;" ::: "memory")
#define CP_WAIT(n)  asm volatile("cp.async.wait_group %0;" :: "n"(n) : "memory")

__device__ __forceinline__ void ldsm4(uint32_t* r, uint32_t addr) {
    asm volatile("ldmatrix.sync.aligned.m8n8.x4.shared.b16 {%0,%1,%2,%3}, [%4];"
                 : "=r"(r[0]), "=r"(r[1]), "=r"(r[2]), "=r"(r[3]) : "r"(addr));
}
__device__ __forceinline__ void mma_fp16(float* d, const uint32_t* a, const uint32_t* b) {
    asm volatile("mma.sync.aligned.m16n8k16.row.col.f32.f16.f16.f32 "
                 "{%0,%1,%2,%3}, {%4,%5,%6,%7}, {%8,%9}, {%0,%1,%2,%3};"
                 : "+f"(d[0]), "+f"(d[1]), "+f"(d[2]), "+f"(d[3])
                 : "r"(a[0]), "r"(a[1]), "r"(a[2]), "r"(a[3]), "r"(b[0]), "r"(b[1]));
}
__device__ __forceinline__ uint32_t pack2h(float a, float b) {
    __half2 t = __floats2half2_rn(a, b);
    return *(uint32_t*)&t;
}

// ---------------------------------------------------------------------------
// Static device scratch (no allocations)
// ---------------------------------------------------------------------------
__device__ __half g_Xh[64u * 1024u * 512u];     // X fp16  [65536,512]
__device__ __half g_Jh[64u * 1024u * 1024u];    // adj fp16 [64,1024,1024]
__device__ __half g_W1h[1024u * 512u];          // W1^T [1024,512]
__device__ __half g_W2h[512u * 1024u];          // W2^T [512,1024]
__device__ __half g_S1h[1024u * 65536u];        // support1^T [1024,65536]
__device__ __half g_H1h[65536u * 1024u];        // h1 [65536,1024]
__device__ __half g_S2h[512u * 65536u];         // support2^T [512,65536]
__device__ float  g_H2[65536u * 512u];          // h2 fp32 [65536,512]

// ---------------------------------------------------------------------------
// fp32 -> fp16 convert (elementwise, float4 -> 4x half)
// ---------------------------------------------------------------------------
__global__ void __launch_bounds__(256)
convert_kernel(const float* __restrict__ src, __half* __restrict__ dst, size_t n4)
{
    size_t stride = (size_t)gridDim.x * blockDim.x;
    for (size_t i = (size_t)blockIdx.x * blockDim.x + threadIdx.x; i < n4; i += stride) {
        float4 v = ((const float4*)src)[i];
        uint2 o;
        o.x = pack2h(v.x, v.y);
        o.y = pack2h(v.z, v.w);
        ((uint2*)dst)[i] = o;
    }
}

// transpose-convert: src[R,C] fp32 -> dst[C,R] fp16
__global__ void __launch_bounds__(256)
tconvert_kernel(const float* __restrict__ src, __half* __restrict__ dst, int R, int C)
{
    int total = R * C;
    for (int idx = blockIdx.x * blockDim.x + threadIdx.x; idx < total;
         idx += gridDim.x * blockDim.x) {
        int r = idx / C, c = idx % C;
        dst[(size_t)c * R + r] = __float2half(src[idx]);
    }
}

// ---------------------------------------------------------------------------
// mma.sync fp16 GEMM: D[128,256] per CTA, 8 warps (2x4), warp tile 64x64.
// EPI: 0 = fp16 out; 1 = bias+ReLU fp16 out; 2 = bias+ReLU fp32 out.
// ---------------------------------------------------------------------------
template <int EPI>
__global__ void __launch_bounds__(256)
mma_gemm(const __half* __restrict__ Ag, int lda, size_t strA,
         const __half* __restrict__ Bg, int ldb, size_t strB,
         const float* __restrict__ bias,
         __half* __restrict__ Ch, float* __restrict__ Cf, int ldc, size_t strC,
         int nch)
{
    extern __shared__ char smem[];
    const uint32_t sb = smem_u32(smem);
    const int tid = threadIdx.x;
    const int wid = tid >> 5;
    const int l   = tid & 31;
    const int warp_m = wid & 1;   // 2 x 64 rows
    const int warp_n = wid >> 1;  // 4 x 64 cols
    const int bz = blockIdx.z;
    const int m0 = blockIdx.y * BM;
    const int n0 = blockIdx.x * BN;

    const __half* pA = Ag + strA * bz;
    const __half* pB = Bg + strB * bz;

    // cp.async staging geometry
    const int ld_row = tid >> 3;   // base row (0..31), +32*it
    const int ld_c16 = tid & 7;    // 16-byte column

    auto load_tiles = [&](int c, int st) {
        const int kbase = c * BK;
        const uint32_t sbase = sb + st * STG;
        #pragma unroll
        for (int it = 0; it < 4; it++) {           // A: 128 rows
            const int row = ld_row + it * 32;
            cp16(sbase + SWZ((uint32_t)(row * 128 + ld_c16 * 16)),
                 pA + (size_t)(m0 + row) * lda + kbase + ld_c16 * 8);
        }
        #pragma unroll
        for (int it = 0; it < 8; it++) {           // B: 256 rows
            const int row = ld_row + it * 32;
            cp16(sbase + A_BYTES + SWZ((uint32_t)(row * 128 + ld_c16 * 16)),
                 pB + (size_t)(n0 + row) * ldb + kbase + ld_c16 * 8);
        }
    };

    // ldmatrix per-lane geometry (verified in R3)
    const int a_row_l = l & 15;
    const uint32_t a_koff = (uint32_t)((l >> 4) * 16);
    const int b_row_l = (l & 7) + ((l >> 4) * 8);
    const uint32_t b_koff = (uint32_t)(((l >> 3) & 1) * 16);

    uint32_t a_rb[4], b_rb[4];
    #pragma unroll
    for (int mi = 0; mi < 4; mi++)
        a_rb[mi] = (uint32_t)((warp_m * 64 + mi * 16 + a_row_l) * 128);
    #pragma unroll
    for (int nb = 0; nb < 4; nb++)
        b_rb[nb] = (uint32_t)((warp_n * 64 + nb * 16 + b_row_l) * 128);

    float acc[4][8][4];
    #pragma unroll
    for (int mi = 0; mi < 4; mi++)
        #pragma unroll
        for (int ni = 0; ni < 8; ni++)
            #pragma unroll
            for (int q = 0; q < 4; q++) acc[mi][ni][q] = 0.0f;

    load_tiles(0, 0);
    CP_COMMIT();
    load_tiles(1, 1);
    CP_COMMIT();

    for (int c = 0; c < nch; c++) {
        if (c + 1 < nch) { CP_WAIT(1); } else { CP_WAIT(0); }
        __syncthreads();
        if (c + 2 < nch) {
            load_tiles(c + 2, (c + 2) % NSTG);
            CP_COMMIT();
        }

        const uint32_t sA = sb + (c % NSTG) * STG;
        const uint32_t sB = sA + A_BYTES;

        #pragma unroll
        for (int ks = 0; ks < 4; ks++) {
            const uint32_t kb = (uint32_t)(ks * 32);
            uint32_t Ah[4][4], Bh[4][4];
            #pragma unroll
            for (int mi = 0; mi < 4; mi++)
                ldsm4(Ah[mi], sA + SWZ(a_rb[mi] + kb + a_koff));
            #pragma unroll
            for (int nb = 0; nb < 4; nb++)
                ldsm4(Bh[nb], sB + SWZ(b_rb[nb] + kb + b_koff));
            #pragma unroll
            for (int mi = 0; mi < 4; mi++)
                #pragma unroll
                for (int ni = 0; ni < 8; ni++)
                    mma_fp16(acc[mi][ni], Ah[mi], &Bh[ni >> 1][(ni & 1) * 2]);
        }
    }

    // ---- epilogue (register-resident, no sync needed) ----
    const int er = warp_m * 64 + (l >> 2);
    const int ec = warp_n * 64 + 2 * (l & 3);
    #pragma unroll
    for (int mi = 0; mi < 4; mi++) {
        const int row = m0 + er + mi * 16;
        const size_t ro0 = strC * bz + (size_t)row * ldc;
        const size_t ro1 = ro0 + (size_t)8 * ldc;
        #pragma unroll
        for (int ni = 0; ni < 8; ni++) {
            const int col = n0 + ec + ni * 8;
            float v00 = acc[mi][ni][0], v01 = acc[mi][ni][1];
            float v10 = acc[mi][ni][2], v11 = acc[mi][ni][3];
            if (EPI >= 1) {
                const float2 bb = *(const float2*)(bias + col);
                v00 = fmaxf(v00 + bb.x, 0.0f);
                v01 = fmaxf(v01 + bb.y, 0.0f);
                v10 = fmaxf(v10 + bb.x, 0.0f);
                v11 = fmaxf(v11 + bb.y, 0.0f);
            }
            if (EPI <= 1) {
                *(uint32_t*)(Ch + ro0 + col) = pack2h(v00, v01);
                *(uint32_t*)(Ch + ro1 + col) = pack2h(v10, v11);
            } else {
                *(float2*)(Cf + ro0 + col) = make_float2(v00, v01);
                *(float2*)(Cf + ro1 + col) = make_float2(v10, v11);
            }
        }
    }
}

// ---------------------------------------------------------------------------
// pool: out[b] = mean_{n<len} h2[b,n,:] . Wl + bl
// ---------------------------------------------------------------------------
__global__ void __launch_bounds__(256)
pool_kernel(const float* __restrict__ h2, const float* __restrict__ Wl,
            const float* __restrict__ bl, const int* __restrict__ length,
            float* __restrict__ out)
{
    __shared__ float sW[512];
    __shared__ float red[256];
    const int b = blockIdx.x;
    const int tid = threadIdx.x;
    for (int i = tid; i < 512; i += 256) sW[i] = Wl[i];
    __syncthreads();
    const int len = length[b];
    const float4* base4 = (const float4*)(h2 + (size_t)b * 1024 * 512);
    const int total4 = (len * 512) >> 2;
    float acc = 0.0f;
    for (int i4 = tid; i4 < total4; i4 += 256) {
        float4 v = base4[i4];
        const int h = (i4 << 2) & 511;
        acc = fmaf(v.x, sW[h + 0], acc);
        acc = fmaf(v.y, sW[h + 1], acc);
        acc = fmaf(v.z, sW[h + 2], acc);
        acc = fmaf(v.w, sW[h + 3], acc);
    }
    red[tid] = acc;
    __syncthreads();
    #pragma unroll
    for (int s = 128; s > 0; s >>= 1) {
        if (tid < s) red[tid] += red[tid + s];
        __syncthreads();
    }
    if (tid == 0) out[b] = red[0] / (float)len + bl[0];
}

// ---------------------------------------------------------------------------
extern "C" void kernel_launch(void* const* d_in, const int* in_sizes, int n_in,
                              void* d_out, int out_size)
{
    const float* x      = (const float*)d_in[0];
    const float* adj    = (const float*)d_in[1];
    const int*   length = (const int*)  d_in[2];
    const float* W1     = (const float*)d_in[3];
    const float* b1     = (const float*)d_in[4];
    const float* W2     = (const float*)d_in[5];
    const float* b2     = (const float*)d_in[6];
    const float* Wl     = (const float*)d_in[7];
    const float* bl     = (const float*)d_in[8];
    float* out = (float*)d_out;

    __half *Xh, *Jh, *W1h, *W2h, *S1h, *H1h, *S2h;
    float* H2;
    cudaGetSymbolAddress((void**)&Xh,  g_Xh);
    cudaGetSymbolAddress((void**)&Jh,  g_Jh);
    cudaGetSymbolAddress((void**)&W1h, g_W1h);
    cudaGetSymbolAddress((void**)&W2h, g_W2h);
    cudaGetSymbolAddress((void**)&S1h, g_S1h);
    cudaGetSymbolAddress((void**)&H1h, g_H1h);
    cudaGetSymbolAddress((void**)&S2h, g_S2h);
    cudaGetSymbolAddress((void**)&H2,  g_H2);

    cudaFuncSetAttribute(mma_gemm<0>, cudaFuncAttributeMaxDynamicSharedMemorySize, SMEM_TOTAL);
    cudaFuncSetAttribute(mma_gemm<1>, cudaFuncAttributeMaxDynamicSharedMemorySize, SMEM_TOTAL);
    cudaFuncSetAttribute(mma_gemm<2>, cudaFuncAttributeMaxDynamicSharedMemorySize, SMEM_TOTAL);

    // converts
    convert_kernel<<<4096, 256>>>(x,   Xh, (size_t)64 * 1024 * 512 / 4);
    convert_kernel<<<8192, 256>>>(adj, Jh, (size_t)64 * 1024 * 1024 / 4);
    tconvert_kernel<<<512, 256>>>(W1, W1h, 512, 1024);
    tconvert_kernel<<<512, 256>>>(W2, W2h, 1024, 512);

    // G1: support1^T[1024,65536] = W1^T @ X^T   (M=1024, N=65536, K=512)
    mma_gemm<0><<<dim3(256, 8, 1), 256, SMEM_TOTAL>>>(
        W1h, 512, 0, Xh, 512, 0, nullptr,
        S1h, nullptr, 65536, 0, 512 / BK);

    // G2: h1[b] = relu(adj[b] @ support1[b] + b1)  (M=1024, N=1024, K=1024) x64
    mma_gemm<1><<<dim3(4, 8, 64), 256, SMEM_TOTAL>>>(
        Jh, 1024, (size_t)1024 * 1024,
        S1h, 65536, 1024, b1,
        H1h, nullptr, 1024, (size_t)1024 * 1024, 1024 / BK);

    // G3: support2^T[512,65536] = W2^T @ h1^T  (M=512, N=65536, K=1024)
    mma_gemm<0><<<dim3(256, 4, 1), 256, SMEM_TOTAL>>>(
        W2h, 1024, 0, H1h, 1024, 0, nullptr,
        S2h, nullptr, 65536, 0, 1024 / BK);

    // G4: h2[b] = relu(adj[b] @ support2[b] + b2)  (M=1024, N=512, K=1024) x64
    mma_gemm<2><<<dim3(2, 8, 64), 256, SMEM_TOTAL>>>(
        Jh, 1024, (size_t)1024 * 1024,
        S2h, 65536, 1024, b2,
        nullptr, H2, 512, (size_t)1024 * 512, 1024 / BK);

    pool_kernel<<<64, 256>>>(H2, Wl, bl, length, out);

    (void)in_sizes; (void)n_in; (void)out_size;
}

// round 5
// speedup vs baseline: 10.6361x; 2.0148x over previous
#include <cuda_runtime.h>
#include <cuda_fp16.h>
#include <stdint.h>

// ===========================================================================
// GCN forward, fp16 mma.sync (fp32 accum), reassociated to minimize MACs:
//   T1: P1[b]   = adj[b] @ x[b]            (M=1024,N=512, K=1024) x64
//   T2: h1      = relu(P1 @ W1 + b1)       (M=65536,N=1024,K=512)
//   T3: S2^T    = W2^T @ h1^T              (M=512,N=65536,K=1024)
//   T4: pool[b]+= mask.(relu(adj[b]@S2[b]+b2) . Wl)   (rows >= len skipped)
//   out[b] = pool[b]/len[b] + bl
// ===========================================================================

#define BM 128
#define BN 256
#define BK 64                       // fp16 per chunk (=128B per row)
#define NSTG 3

#define A_BYTES (BM * 128)
#define B_BYTES (BN * 128)
#define STG     (A_BYTES + B_BYTES)
#define SMEM_TOTAL (NSTG * STG)     // 147456

#define SWZ(off) ((off) ^ (((off) >> 3) & 0x70))

__device__ __forceinline__ uint32_t smem_u32(const void* p) {
    uint32_t a;
    asm("{ .reg .u64 t; cvta.to.shared.u64 t, %1; cvt.u32.u64 %0, t; }" : "=r"(a) : "l"(p));
    return a;
}
__device__ __forceinline__ void cp16(uint32_t dst, const void* src) {
    asm volatile("cp.async.cg.shared.global [%0], [%1], 16;" :: "r"(dst), "l"(src));
}
#define CP_COMMIT() asm volatile("cp.async.commit_group;" ::: "memory")
#define CP_WAIT(n)  asm volatile("cp.async.wait_group %0;" :: "n"(n) : "memory")

__device__ __forceinline__ void ldsm4(uint32_t* r, uint32_t addr) {
    asm volatile("ldmatrix.sync.aligned.m8n8.x4.shared.b16 {%0,%1,%2,%3}, [%4];"
                 : "=r"(r[0]), "=r"(r[1]), "=r"(r[2]), "=r"(r[3]) : "r"(addr));
}
__device__ __forceinline__ void mma_fp16(float* d, const uint32_t* a, const uint32_t* b) {
    asm volatile("mma.sync.aligned.m16n8k16.row.col.f32.f16.f16.f32 "
                 "{%0,%1,%2,%3}, {%4,%5,%6,%7}, {%8,%9}, {%0,%1,%2,%3};"
                 : "+f"(d[0]), "+f"(d[1]), "+f"(d[2]), "+f"(d[3])
                 : "r"(a[0]), "r"(a[1]), "r"(a[2]), "r"(a[3]), "r"(b[0]), "r"(b[1]));
}
__device__ __forceinline__ uint32_t pack2h(float a, float b) {
    __half2 t = __floats2half2_rn(a, b);
    return *(uint32_t*)&t;
}

// ---------------------------------------------------------------------------
// Static device scratch
// ---------------------------------------------------------------------------
__device__ __half g_Jh[64u * 1024u * 1024u];    // adj fp16
__device__ __half g_XT[64u * 512u * 1024u];     // x^T per batch [b][f][n]
__device__ __half g_W1T[1024u * 512u];          // W1^T [h1][f]
__device__ __half g_W2T[512u * 1024u];          // W2^T [h2][h1]
__device__ __half g_P1[65536u * 512u];          // adj@x  [n][f]
__device__ __half g_H1[65536u * 1024u];         // h1 [n][h1]
__device__ __half g_S2T[512u * 65536u];         // support2^T [h2][b*1024+n]
__device__ float  g_pool[64];

// ---------------------------------------------------------------------------
__global__ void __launch_bounds__(256)
convert_kernel(const float* __restrict__ src, __half* __restrict__ dst, size_t n4)
{
    size_t stride = (size_t)gridDim.x * blockDim.x;
    for (size_t i = (size_t)blockIdx.x * blockDim.x + threadIdx.x; i < n4; i += stride) {
        float4 v = ((const float4*)src)[i];
        uint2 o;
        o.x = pack2h(v.x, v.y);
        o.y = pack2h(v.z, v.w);
        ((uint2*)dst)[i] = o;
    }
}

// batched transpose-convert: x[b,n,f] fp32 -> xT[b,f,n] fp16 (32x32 smem tiles)
__global__ void __launch_bounds__(256)
xtrans_kernel(const float* __restrict__ src, __half* __restrict__ dst)
{
    __shared__ float tile[32][33];
    const int b = blockIdx.z;
    const int n0 = blockIdx.y * 32;
    const int f0 = blockIdx.x * 32;
    const int tx = threadIdx.x;         // 0..31
    const int ty = threadIdx.y;         // 0..7
    const float* s = src + ((size_t)b * 1024 + n0) * 512 + f0;
    #pragma unroll
    for (int i = ty; i < 32; i += 8) tile[i][tx] = s[(size_t)i * 512 + tx];
    __syncthreads();
    __half* d = dst + ((size_t)b * 512 + f0) * 1024 + n0;
    #pragma unroll
    for (int i = ty; i < 32; i += 8) d[(size_t)i * 1024 + tx] = __float2half(tile[tx][i]);
}

// transpose-convert small weights: src[R,C] fp32 -> dst[C,R] fp16
__global__ void __launch_bounds__(256)
tconvert_kernel(const float* __restrict__ src, __half* __restrict__ dst, int R, int C)
{
    int total = R * C;
    for (int idx = blockIdx.x * blockDim.x + threadIdx.x; idx < total;
         idx += gridDim.x * blockDim.x) {
        int r = idx / C, c = idx % C;
        dst[(size_t)c * R + r] = __float2half(src[idx]);
    }
}

// ---------------------------------------------------------------------------
// mma.sync fp16 GEMM: D[128,256] per CTA, 8 warps (2x4), warp tile 64x64.
// EPI: 0 = fp16 out; 1 = bias+ReLU fp16 out; 3 = bias+ReLU+masked pool.Wl.
// ---------------------------------------------------------------------------
template <int EPI>
__global__ void __launch_bounds__(256)
mma_gemm(const __half* __restrict__ Ag, int lda, size_t strA,
         const __half* __restrict__ Bg, int ldb, size_t strB,
         const float* __restrict__ bias,
         __half* __restrict__ Ch, int ldc, size_t strC,
         const float* __restrict__ Wl, const int* __restrict__ length,
         float* __restrict__ pool,
         int nch)
{
    extern __shared__ char smem[];
    const int bz = blockIdx.z;
    const int m0 = blockIdx.y * BM;
    const int n0 = blockIdx.x * BN;

    int len = 0;
    if (EPI == 3) {
        len = length[bz];
        if (m0 >= len) return;       // rows entirely unused by the pool
    }

    const uint32_t sb = smem_u32(smem);
    const int tid = threadIdx.x;
    const int wid = tid >> 5;
    const int l   = tid & 31;
    const int warp_m = wid & 1;
    const int warp_n = wid >> 1;

    const __half* pA = Ag + strA * bz;
    const __half* pB = Bg + strB * bz;

    const int ld_row = tid >> 3;
    const int ld_c16 = tid & 7;

    auto load_tiles = [&](int c, int st) {
        const int kbase = c * BK;
        const uint32_t sbase = sb + st * STG;
        #pragma unroll
        for (int it = 0; it < 4; it++) {
            const int row = ld_row + it * 32;
            cp16(sbase + SWZ((uint32_t)(row * 128 + ld_c16 * 16)),
                 pA + (size_t)(m0 + row) * lda + kbase + ld_c16 * 8);
        }
        #pragma unroll
        for (int it = 0; it < 8; it++) {
            const int row = ld_row + it * 32;
            cp16(sbase + A_BYTES + SWZ((uint32_t)(row * 128 + ld_c16 * 16)),
                 pB + (size_t)(n0 + row) * ldb + kbase + ld_c16 * 8);
        }
    };

    const int a_row_l = l & 15;
    const uint32_t a_koff = (uint32_t)((l >> 4) * 16);
    const int b_row_l = (l & 7) + ((l >> 4) * 8);
    const uint32_t b_koff = (uint32_t)(((l >> 3) & 1) * 16);

    uint32_t a_rb[4], b_rb[4];
    #pragma unroll
    for (int mi = 0; mi < 4; mi++)
        a_rb[mi] = (uint32_t)((warp_m * 64 + mi * 16 + a_row_l) * 128);
    #pragma unroll
    for (int nb = 0; nb < 4; nb++)
        b_rb[nb] = (uint32_t)((warp_n * 64 + nb * 16 + b_row_l) * 128);

    float acc[4][8][4];
    #pragma unroll
    for (int mi = 0; mi < 4; mi++)
        #pragma unroll
        for (int ni = 0; ni < 8; ni++)
            #pragma unroll
            for (int q = 0; q < 4; q++) acc[mi][ni][q] = 0.0f;

    load_tiles(0, 0);
    CP_COMMIT();
    load_tiles(1, 1);
    CP_COMMIT();

    for (int c = 0; c < nch; c++) {
        if (c + 1 < nch) { CP_WAIT(1); } else { CP_WAIT(0); }
        __syncthreads();
        if (c + 2 < nch) {
            load_tiles(c + 2, (c + 2) % NSTG);
            CP_COMMIT();
        }

        const uint32_t sA = sb + (c % NSTG) * STG;
        const uint32_t sB = sA + A_BYTES;

        #pragma unroll
        for (int ks = 0; ks < 4; ks++) {
            const uint32_t kb = (uint32_t)(ks * 32);
            uint32_t Ah[4][4], Bh[4][4];
            #pragma unroll
            for (int mi = 0; mi < 4; mi++)
                ldsm4(Ah[mi], sA + SWZ(a_rb[mi] + kb + a_koff));
            #pragma unroll
            for (int nb = 0; nb < 4; nb++)
                ldsm4(Bh[nb], sB + SWZ(b_rb[nb] + kb + b_koff));
            #pragma unroll
            for (int mi = 0; mi < 4; mi++)
                #pragma unroll
                for (int ni = 0; ni < 8; ni++)
                    mma_fp16(acc[mi][ni], Ah[mi], &Bh[ni >> 1][(ni & 1) * 2]);
        }
    }

    // ---- epilogue ----
    const int er = warp_m * 64 + (l >> 2);
    const int ec = warp_n * 64 + 2 * (l & 3);

    if (EPI <= 1) {
        #pragma unroll
        for (int mi = 0; mi < 4; mi++) {
            const int row = m0 + er + mi * 16;
            const size_t ro0 = strC * bz + (size_t)row * ldc;
            const size_t ro1 = ro0 + (size_t)8 * ldc;
            #pragma unroll
            for (int ni = 0; ni < 8; ni++) {
                const int col = n0 + ec + ni * 8;
                float v00 = acc[mi][ni][0], v01 = acc[mi][ni][1];
                float v10 = acc[mi][ni][2], v11 = acc[mi][ni][3];
                if (EPI == 1) {
                    const float2 bb = *(const float2*)(bias + col);
                    v00 = fmaxf(v00 + bb.x, 0.0f);
                    v01 = fmaxf(v01 + bb.y, 0.0f);
                    v10 = fmaxf(v10 + bb.x, 0.0f);
                    v11 = fmaxf(v11 + bb.y, 0.0f);
                }
                *(uint32_t*)(Ch + ro0 + col) = pack2h(v00, v01);
                *(uint32_t*)(Ch + ro1 + col) = pack2h(v10, v11);
            }
        }
    } else {
        // EPI==3: bias + ReLU + masked dot with Wl, reduce, atomicAdd per batch
        float part = 0.0f;
        #pragma unroll
        for (int mi = 0; mi < 4; mi++) {
            const int grow0 = m0 + er + mi * 16;
            const bool k0 = grow0 < len;
            const bool k1 = grow0 + 8 < len;
            #pragma unroll
            for (int ni = 0; ni < 8; ni++) {
                const int col = n0 + ec + ni * 8;
                const float2 bb = *(const float2*)(bias + col);
                const float2 wl = *(const float2*)(Wl + col);
                float v00 = fmaxf(acc[mi][ni][0] + bb.x, 0.0f);
                float v01 = fmaxf(acc[mi][ni][1] + bb.y, 0.0f);
                float v10 = fmaxf(acc[mi][ni][2] + bb.x, 0.0f);
                float v11 = fmaxf(acc[mi][ni][3] + bb.y, 0.0f);
                if (k0) part += v00 * wl.x + v01 * wl.y;
                if (k1) part += v10 * wl.x + v11 * wl.y;
            }
        }
        #pragma unroll
        for (int o = 16; o > 0; o >>= 1)
            part += __shfl_xor_sync(0xFFFFFFFFu, part, o);
        __syncthreads();                    // mainloop smem reads complete
        float* red = (float*)smem;
        if (l == 0) red[wid] = part;
        __syncthreads();
        if (tid == 0) {
            float s = 0.0f;
            #pragma unroll
            for (int i = 0; i < 8; i++) s += red[i];
            atomicAdd(pool + bz, s);
        }
    }
}

// ---------------------------------------------------------------------------
__global__ void zero_pool_kernel(float* __restrict__ pool)
{
    pool[threadIdx.x] = 0.0f;
}

__global__ void final_kernel(const float* __restrict__ pool,
                             const int* __restrict__ length,
                             const float* __restrict__ bl,
                             float* __restrict__ out)
{
    const int b = threadIdx.x;
    out[b] = pool[b] / (float)length[b] + bl[0];
}

// ---------------------------------------------------------------------------
extern "C" void kernel_launch(void* const* d_in, const int* in_sizes, int n_in,
                              void* d_out, int out_size)
{
    const float* x      = (const float*)d_in[0];
    const float* adj    = (const float*)d_in[1];
    const int*   length = (const int*)  d_in[2];
    const float* W1     = (const float*)d_in[3];
    const float* b1     = (const float*)d_in[4];
    const float* W2     = (const float*)d_in[5];
    const float* b2     = (const float*)d_in[6];
    const float* Wl     = (const float*)d_in[7];
    const float* bl     = (const float*)d_in[8];
    float* out = (float*)d_out;

    __half *Jh, *XT, *W1T, *W2T, *P1, *H1, *S2T;
    float* pool;
    cudaGetSymbolAddress((void**)&Jh,  g_Jh);
    cudaGetSymbolAddress((void**)&XT,  g_XT);
    cudaGetSymbolAddress((void**)&W1T, g_W1T);
    cudaGetSymbolAddress((void**)&W2T, g_W2T);
    cudaGetSymbolAddress((void**)&P1,  g_P1);
    cudaGetSymbolAddress((void**)&H1,  g_H1);
    cudaGetSymbolAddress((void**)&S2T, g_S2T);
    cudaGetSymbolAddress((void**)&pool, g_pool);

    cudaFuncSetAttribute(mma_gemm<0>, cudaFuncAttributeMaxDynamicSharedMemorySize, SMEM_TOTAL);
    cudaFuncSetAttribute(mma_gemm<1>, cudaFuncAttributeMaxDynamicSharedMemorySize, SMEM_TOTAL);
    cudaFuncSetAttribute(mma_gemm<3>, cudaFuncAttributeMaxDynamicSharedMemorySize, SMEM_TOTAL);

    // converts
    convert_kernel<<<8192, 256>>>(adj, Jh, (size_t)64 * 1024 * 1024 / 4);
    xtrans_kernel<<<dim3(16, 32, 64), dim3(32, 8)>>>(x, XT);
    tconvert_kernel<<<512, 256>>>(W1, W1T, 512, 1024);
    tconvert_kernel<<<512, 256>>>(W2, W2T, 1024, 512);

    // T1: P1[b] = adj[b] @ x[b]   (M=1024, N=512, K=1024) x64
    mma_gemm<0><<<dim3(2, 8, 64), 256, SMEM_TOTAL>>>(
        Jh, 1024, (size_t)1024 * 1024,
        XT, 1024, (size_t)512 * 1024,
        nullptr, P1, 512, (size_t)1024 * 512,
        nullptr, nullptr, nullptr, 1024 / BK);

    // T2: h1 = relu(P1 @ W1 + b1)  (M=65536, N=1024, K=512)
    mma_gemm<1><<<dim3(4, 512, 1), 256, SMEM_TOTAL>>>(
        P1, 512, 0,
        W1T, 512, 0,
        b1, H1, 1024, 0,
        nullptr, nullptr, nullptr, 512 / BK);

    // T3: S2^T = W2^T @ h1^T  (M=512, N=65536, K=1024)
    mma_gemm<0><<<dim3(256, 4, 1), 256, SMEM_TOTAL>>>(
        W2T, 1024, 0,
        H1, 1024, 0,
        nullptr, S2T, 65536, 0,
        nullptr, nullptr, nullptr, 1024 / BK);

    // T4: fused relu(adj[b]@S2[b]+b2) . Wl with row mask, row-block skip
    zero_pool_kernel<<<1, 64>>>(pool);
    mma_gemm<3><<<dim3(2, 8, 64), 256, SMEM_TOTAL>>>(
        Jh, 1024, (size_t)1024 * 1024,
        S2T, 65536, 1024,
        b2, nullptr, 0, 0,
        Wl, length, pool, 1024 / BK);

    final_kernel<<<1, 64>>>(pool, length, bl, out);

    (void)in_sizes; (void)n_in; (void)out_size;
}

// round 7
// speedup vs baseline: 10.7293x; 1.0088x over previous
#include <cuda_runtime.h>
#include <cuda_fp16.h>
#include <stdint.h>

// ===========================================================================
// GCN forward, fp16 mma.sync (fp32 accum), reassociated to minimize MACs:
//   T1: P1[b]   = adj[b] @ x[b]            (M=1024,N=512, K=1024) x64
//   T2: h1      = relu(P1 @ W1 + b1)       (M=65536,N=1024,K=512)
//   T3: S2^T    = W2^T @ h1^T              (M=512,N=65536,K=1024)  [SWAP grid]
//   T4: pool[b]+= mask.(relu(adj[b]@S2[b]+b2) . Wl)   (rows >= len skipped)
//   out[b] = pool[b]/len[b] + bl
// ===========================================================================

#define BM 128
#define BN 256
#define BK 64                       // fp16 per chunk (=128B per row)
#define NSTG 4

#define A_BYTES (BM * 128)
#define B_BYTES (BN * 128)
#define STG     (A_BYTES + B_BYTES)
#define SMEM_TOTAL (NSTG * STG)     // 196608

#define SWZ(off) ((off) ^ (((off) >> 3) & 0x70))

__device__ __forceinline__ uint32_t smem_u32(const void* p) {
    uint32_t a;
    asm("{ .reg .u64 t; cvta.to.shared.u64 t, %1; cvt.u32.u64 %0, t; }" : "=r"(a) : "l"(p));
    return a;
}
__device__ __forceinline__ void cp16(uint32_t dst, const void* src) {
    asm volatile("cp.async.cg.shared.global [%0], [%1], 16;" :: "r"(dst), "l"(src));
}
#define CP_COMMIT() asm volatile("cp.async.commit_group;" ::: "memory")
#define CP_WAIT(n)  asm volatile("cp.async.wait_group %0;" :: "n"(n) : "memory")

__device__ __forceinline__ void ldsm4(uint32_t* r, uint32_t addr) {
    asm volatile("ldmatrix.sync.aligned.m8n8.x4.shared.b16 {%0,%1,%2,%3}, [%4];"
                 : "=r"(r[0]), "=r"(r[1]), "=r"(r[2]), "=r"(r[3]) : "r"(addr));
}
__device__ __forceinline__ void mma_fp16(float* d, const uint32_t* a, const uint32_t* b) {
    asm volatile("mma.sync.aligned.m16n8k16.row.col.f32.f16.f16.f32 "
                 "{%0,%1,%2,%3}, {%4,%5,%6,%7}, {%8,%9}, {%0,%1,%2,%3};"
                 : "+f"(d[0]), "+f"(d[1]), "+f"(d[2]), "+f"(d[3])
                 : "r"(a[0]), "r"(a[1]), "r"(a[2]), "r"(a[3]), "r"(b[0]), "r"(b[1]));
}
__device__ __forceinline__ uint32_t pack2h(float a, float b) {
    __half2 t = __floats2half2_rn(a, b);
    return *(uint32_t*)&t;
}

// ---------------------------------------------------------------------------
// Static device scratch
// ---------------------------------------------------------------------------
__device__ __half g_Jh[64u * 1024u * 1024u];    // adj fp16
__device__ __half g_XT[64u * 512u * 1024u];     // x^T per batch [b][f][n]
__device__ __half g_W1T[1024u * 512u];          // W1^T [h1][f]
__device__ __half g_W2T[512u * 1024u];          // W2^T [h2][h1]
__device__ __half g_P1[65536u * 512u];          // adj@x  [n][f]
__device__ __half g_H1[65536u * 1024u];         // h1 [n][h1]
__device__ __half g_S2T[512u * 65536u];         // support2^T [h2][b*1024+n]
__device__ float  g_pool[64];

// ---------------------------------------------------------------------------
__global__ void __launch_bounds__(256)
convert_kernel(const float* __restrict__ src, __half* __restrict__ dst, size_t n4)
{
    size_t stride = (size_t)gridDim.x * blockDim.x;
    for (size_t i = (size_t)blockIdx.x * blockDim.x + threadIdx.x; i < n4; i += stride) {
        float4 v = ((const float4*)src)[i];
        uint2 o;
        o.x = pack2h(v.x, v.y);
        o.y = pack2h(v.z, v.w);
        ((uint2*)dst)[i] = o;
    }
}

// batched transpose-convert: x[b,n,f] fp32 -> xT[b,f,n] fp16 (32x32 smem tiles)
__global__ void __launch_bounds__(256)
xtrans_kernel(const float* __restrict__ src, __half* __restrict__ dst)
{
    __shared__ float tile[32][33];
    const int b = blockIdx.z;
    const int n0 = blockIdx.y * 32;
    const int f0 = blockIdx.x * 32;
    const int tx = threadIdx.x;
    const int ty = threadIdx.y;
    const float* s = src + ((size_t)b * 1024 + n0) * 512 + f0;
    #pragma unroll
    for (int i = ty; i < 32; i += 8) tile[i][tx] = s[(size_t)i * 512 + tx];
    __syncthreads();
    __half* d = dst + ((size_t)b * 512 + f0) * 1024 + n0;
    #pragma unroll
    for (int i = ty; i < 32; i += 8) d[(size_t)i * 1024 + tx] = __float2half(tile[tx][i]);
}

// transpose-convert small weights: src[R,C] fp32 -> dst[C,R] fp16
__global__ void __launch_bounds__(256)
tconvert_kernel(const float* __restrict__ src, __half* __restrict__ dst, int R, int C)
{
    int total = R * C;
    for (int idx = blockIdx.x * blockDim.x + threadIdx.x; idx < total;
         idx += gridDim.x * blockDim.x) {
        int r = idx / C, c = idx % C;
        dst[(size_t)c * R + r] = __float2half(src[idx]);
    }
}

// ---------------------------------------------------------------------------
// mma.sync fp16 GEMM: D[128,256] per CTA, 8 warps (2x4), warp tile 64x64.
// EPI: 0 = fp16 out; 1 = bias+ReLU fp16 out; 3 = bias+ReLU+masked pool.Wl.
// SWAP: blockIdx.x indexes M (keeps co-scheduled CTAs on the same B rows).
// ---------------------------------------------------------------------------
template <int EPI, bool SWAP>
__global__ void __launch_bounds__(256)
mma_gemm(const __half* __restrict__ Ag, int lda, size_t strA,
         const __half* __restrict__ Bg, int ldb, size_t strB,
         const float* __restrict__ bias,
         __half* __restrict__ Ch, int ldc, size_t strC,
         const float* __restrict__ Wl, const int* __restrict__ length,
         float* __restrict__ pool,
         int nch)
{
    extern __shared__ char smem[];
    const int bz = blockIdx.z;
    const int m0 = (SWAP ? blockIdx.x : blockIdx.y) * BM;
    const int n0 = (SWAP ? blockIdx.y : blockIdx.x) * BN;

    int len = 0;
    if (EPI == 3) {
        len = length[bz];
        if (m0 >= len) return;
    }

    const uint32_t sb = smem_u32(smem);
    const int tid = threadIdx.x;
    const int wid = tid >> 5;
    const int l   = tid & 31;
    const int warp_m = wid & 1;
    const int warp_n = wid >> 1;

    const __half* pA = Ag + strA * bz;
    const __half* pB = Bg + strB * bz;

    const int ld_row = tid >> 3;
    const int ld_c16 = tid & 7;

    auto load_tiles = [&](int c, int st) {
        const int kbase = c * BK;
        const uint32_t sbase = sb + st * STG;
        #pragma unroll
        for (int it = 0; it < 4; it++) {
            const int row = ld_row + it * 32;
            cp16(sbase + SWZ((uint32_t)(row * 128 + ld_c16 * 16)),
                 pA + (size_t)(m0 + row) * lda + kbase + ld_c16 * 8);
        }
        #pragma unroll
        for (int it = 0; it < 8; it++) {
            const int row = ld_row + it * 32;
            cp16(sbase + A_BYTES + SWZ((uint32_t)(row * 128 + ld_c16 * 16)),
                 pB + (size_t)(n0 + row) * ldb + kbase + ld_c16 * 8);
        }
    };

    const int a_row_l = l & 15;
    const uint32_t a_koff = (uint32_t)((l >> 4) * 16);
    const int b_row_l = (l & 7) + ((l >> 4) * 8);
    const uint32_t b_koff = (uint32_t)(((l >> 3) & 1) * 16);

    uint32_t a_rb[4], b_rb[4];
    #pragma unroll
    for (int mi = 0; mi < 4; mi++)
        a_rb[mi] = (uint32_t)((warp_m * 64 + mi * 16 + a_row_l) * 128);
    #pragma unroll
    for (int nb = 0; nb < 4; nb++)
        b_rb[nb] = (uint32_t)((warp_n * 64 + nb * 16 + b_row_l) * 128);

    float acc[4][8][4];
    #pragma unroll
    for (int mi = 0; mi < 4; mi++)
        #pragma unroll
        for (int ni = 0; ni < 8; ni++)
            #pragma unroll
            for (int q = 0; q < 4; q++) acc[mi][ni][q] = 0.0f;

    // prologue: prefetch up to NSTG-1 chunks
    load_tiles(0, 0);
    CP_COMMIT();
    if (1 < nch) { load_tiles(1, 1); CP_COMMIT(); }
    if (2 < nch) { load_tiles(2, 2); CP_COMMIT(); }

    for (int c = 0; c < nch; c++) {
        if (c + 2 < nch)      { CP_WAIT(2); }
        else if (c + 1 < nch) { CP_WAIT(1); }
        else                  { CP_WAIT(0); }
        __syncthreads();
        if (c + 3 < nch) {
            load_tiles(c + 3, (c + 3) & 3);
            CP_COMMIT();
        }

        const uint32_t sA = sb + (c & 3) * STG;
        const uint32_t sB = sA + A_BYTES;

        #pragma unroll
        for (int ks = 0; ks < 4; ks++) {
            const uint32_t kb = (uint32_t)(ks * 32);
            uint32_t Ah[4][4], Bh[4][4];
            #pragma unroll
            for (int mi = 0; mi < 4; mi++)
                ldsm4(Ah[mi], sA + SWZ(a_rb[mi] + kb + a_koff));
            #pragma unroll
            for (int nb = 0; nb < 4; nb++)
                ldsm4(Bh[nb], sB + SWZ(b_rb[nb] + kb + b_koff));
            #pragma unroll
            for (int mi = 0; mi < 4; mi++)
                #pragma unroll
                for (int ni = 0; ni < 8; ni++)
                    mma_fp16(acc[mi][ni], Ah[mi], &Bh[ni >> 1][(ni & 1) * 2]);
        }
    }

    // ---- epilogue ----
    const int er = warp_m * 64 + (l >> 2);
    const int ec = warp_n * 64 + 2 * (l & 3);

    if (EPI <= 1) {
        #pragma unroll
        for (int mi = 0; mi < 4; mi++) {
            const int row = m0 + er + mi * 16;
            const size_t ro0 = strC * bz + (size_t)row * ldc;
            const size_t ro1 = ro0 + (size_t)8 * ldc;
            #pragma unroll
            for (int ni = 0; ni < 8; ni++) {
                const int col = n0 + ec + ni * 8;
                float v00 = acc[mi][ni][0], v01 = acc[mi][ni][1];
                float v10 = acc[mi][ni][2], v11 = acc[mi][ni][3];
                if (EPI == 1) {
                    const float2 bb = *(const float2*)(bias + col);
                    v00 = fmaxf(v00 + bb.x, 0.0f);
                    v01 = fmaxf(v01 + bb.y, 0.0f);
                    v10 = fmaxf(v10 + bb.x, 0.0f);
                    v11 = fmaxf(v11 + bb.y, 0.0f);
                }
                *(uint32_t*)(Ch + ro0 + col) = pack2h(v00, v01);
                *(uint32_t*)(Ch + ro1 + col) = pack2h(v10, v11);
            }
        }
    } else {
        // EPI==3: bias + ReLU + masked dot with Wl, reduce, atomicAdd per batch
        float part = 0.0f;
        #pragma unroll
        for (int mi = 0; mi < 4; mi++) {
            const int grow0 = m0 + er + mi * 16;
            const bool k0 = grow0 < len;
            const bool k1 = grow0 + 8 < len;
            #pragma unroll
            for (int ni = 0; ni < 8; ni++) {
                const int col = n0 + ec + ni * 8;
                const float2 bb = *(const float2*)(bias + col);
                const float2 wl = *(const float2*)(Wl + col);
                float v00 = fmaxf(acc[mi][ni][0] + bb.x, 0.0f);
                float v01 = fmaxf(acc[mi][ni][1] + bb.y, 0.0f);
                float v10 = fmaxf(acc[mi][ni][2] + bb.x, 0.0f);
                float v11 = fmaxf(acc[mi][ni][3] + bb.y, 0.0f);
                if (k0) part += v00 * wl.x + v01 * wl.y;
                if (k1) part += v10 * wl.x + v11 * wl.y;
            }
        }
        #pragma unroll
        for (int o = 16; o > 0; o >>= 1)
            part += __shfl_xor_sync(0xFFFFFFFFu, part, o);
        __syncthreads();
        float* red = (float*)smem;
        if (l == 0) red[wid] = part;
        __syncthreads();
        if (tid == 0) {
            float s = 0.0f;
            #pragma unroll
            for (int i = 0; i < 8; i++) s += red[i];
            atomicAdd(pool + bz, s);
        }
    }
}

// ---------------------------------------------------------------------------
__global__ void zero_pool_kernel(float* __restrict__ pool)
{
    pool[threadIdx.x] = 0.0f;
}

__global__ void final_kernel(const float* __restrict__ pool,
                             const int* __restrict__ length,
                             const float* __restrict__ bl,
                             float* __restrict__ out)
{
    const int b = threadIdx.x;
    out[b] = pool[b] / (float)length[b] + bl[0];
}

// ---------------------------------------------------------------------------
extern "C" void kernel_launch(void* const* d_in, const int* in_sizes, int n_in,
                              void* d_out, int out_size)
{
    const float* x      = (const float*)d_in[0];
    const float* adj    = (const float*)d_in[1];
    const int*   length = (const int*)  d_in[2];
    const float* W1     = (const float*)d_in[3];
    const float* b1     = (const float*)d_in[4];
    const float* W2     = (const float*)d_in[5];
    const float* b2     = (const float*)d_in[6];
    const float* Wl     = (const float*)d_in[7];
    const float* bl     = (const float*)d_in[8];
    float* out = (float*)d_out;

    __half *Jh, *XT, *W1T, *W2T, *P1, *H1, *S2T;
    float* pool;
    cudaGetSymbolAddress((void**)&Jh,  g_Jh);
    cudaGetSymbolAddress((void**)&XT,  g_XT);
    cudaGetSymbolAddress((void**)&W1T, g_W1T);
    cudaGetSymbolAddress((void**)&W2T, g_W2T);
    cudaGetSymbolAddress((void**)&P1,  g_P1);
    cudaGetSymbolAddress((void**)&H1,  g_H1);
    cudaGetSymbolAddress((void**)&S2T, g_S2T);
    cudaGetSymbolAddress((void**)&pool, g_pool);

    cudaFuncSetAttribute(mma_gemm<0, false>, cudaFuncAttributeMaxDynamicSharedMemorySize, SMEM_TOTAL);
    cudaFuncSetAttribute(mma_gemm<1, false>, cudaFuncAttributeMaxDynamicSharedMemorySize, SMEM_TOTAL);
    cudaFuncSetAttribute(mma_gemm<0, true>,  cudaFuncAttributeMaxDynamicSharedMemorySize, SMEM_TOTAL);
    cudaFuncSetAttribute(mma_gemm<3, false>, cudaFuncAttributeMaxDynamicSharedMemorySize, SMEM_TOTAL);

    // converts
    convert_kernel<<<8192, 256>>>(adj, Jh, (size_t)64 * 1024 * 1024 / 4);
    xtrans_kernel<<<dim3(16, 32, 64), dim3(32, 8)>>>(x, XT);
    tconvert_kernel<<<512, 256>>>(W1, W1T, 512, 1024);
    tconvert_kernel<<<512, 256>>>(W2, W2T, 1024, 512);

    // T1: P1[b] = adj[b] @ x[b]   (M=1024, N=512, K=1024) x64
    mma_gemm<0, false><<<dim3(2, 8, 64), 256, SMEM_TOTAL>>>(
        Jh, 1024, (size_t)1024 * 1024,
        XT, 1024, (size_t)512 * 1024,
        nullptr, P1, 512, (size_t)1024 * 512,
        nullptr, nullptr, nullptr, 1024 / BK);

    // T2: h1 = relu(P1 @ W1 + b1)  (M=65536, N=1024, K=512)
    mma_gemm<1, false><<<dim3(4, 512, 1), 256, SMEM_TOTAL>>>(
        P1, 512, 0,
        W1T, 512, 0,
        b1, H1, 1024, 0,
        nullptr, nullptr, nullptr, 512 / BK);

    // T3: S2^T = W2^T @ h1^T  (M=512, N=65536, K=1024), SWAP grid so the
    // 4 co-scheduled M-blocks share each h1 row-group through L2.
    mma_gemm<0, true><<<dim3(4, 256, 1), 256, SMEM_TOTAL>>>(
        W2T, 1024, 0,
        H1, 1024, 0,
        nullptr, S2T, 65536, 0,
        nullptr, nullptr, nullptr, 1024 / BK);

    // T4: fused relu(adj[b]@S2[b]+b2) . Wl with row mask, row-block skip
    zero_pool_kernel<<<1, 64>>>(pool);
    mma_gemm<3, false><<<dim3(2, 8, 64), 256, SMEM_TOTAL>>>(
        Jh, 1024, (size_t)1024 * 1024,
        S2T, 65536, 1024,
        b2, nullptr, 0, 0,
        Wl, length, pool, 1024 / BK);

    final_kernel<<<1, 64>>>(pool, length, bl, out);

    (void)in_sizes; (void)n_in; (void)out_size;
}

// round 8
// speedup vs baseline: 11.5219x; 1.0739x over previous
#include <cuda_runtime.h>
#include <cuda_fp16.h>
#include <stdint.h>

// ===========================================================================
// GCN forward, fp16 mma.sync (fp32 accum), reassociated to minimize MACs:
//   T1: P1[b]   = adj[b] @ x[b]            (M=1024,N=512, K=1024) x64
//   T2: h1      = relu(P1 @ W1 + b1)       (M=65536,N=1024,K=512)
//   T3: S2^T    = W2^T @ h1^T              (M=512,N=65536,K=1024)  [SWAP grid]
//   T4: pool[b]+= mask.(relu(adj[b]@S2[b]+b2) . Wl)   (rows >= len skipped)
//   out[b] = pool[b]/len[b] + bl
// R7: CTA tile 128x128, warp tile 64x32, 96KB smem -> 2 CTAs/SM to hide
// prologue/epilogue/barrier bubbles (R6 showed we are issue/occupancy bound,
// not DRAM bound).
// ===========================================================================

#define BM 128
#define BN 128
#define BK 64                       // fp16 per chunk (=128B per row)
#define NSTG 3

#define A_BYTES (BM * 128)          // 16384
#define B_BYTES (BN * 128)          // 16384
#define STG     (A_BYTES + B_BYTES) // 32768
#define SMEM_TOTAL (NSTG * STG)     // 98304

#define SWZ(off) ((off) ^ (((off) >> 3) & 0x70))

__device__ __forceinline__ uint32_t smem_u32(const void* p) {
    uint32_t a;
    asm("{ .reg .u64 t; cvta.to.shared.u64 t, %1; cvt.u32.u64 %0, t; }" : "=r"(a) : "l"(p));
    return a;
}
__device__ __forceinline__ void cp16(uint32_t dst, const void* src) {
    asm volatile("cp.async.cg.shared.global [%0], [%1], 16;" :: "r"(dst), "l"(src));
}
#define CP_COMMIT() asm volatile("cp.async.commit_group;" ::: "memory")
#define CP_WAIT(n)  asm volatile("cp.async.wait_group %0;" :: "n"(n) : "memory")

__device__ __forceinline__ void ldsm4(uint32_t* r, uint32_t addr) {
    asm volatile("ldmatrix.sync.aligned.m8n8.x4.shared.b16 {%0,%1,%2,%3}, [%4];"
                 : "=r"(r[0]), "=r"(r[1]), "=r"(r[2]), "=r"(r[3]) : "r"(addr));
}
__device__ __forceinline__ void mma_fp16(float* d, const uint32_t* a, const uint32_t* b) {
    asm volatile("mma.sync.aligned.m16n8k16.row.col.f32.f16.f16.f32 "
                 "{%0,%1,%2,%3}, {%4,%5,%6,%7}, {%8,%9}, {%0,%1,%2,%3};"
                 : "+f"(d[0]), "+f"(d[1]), "+f"(d[2]), "+f"(d[3])
                 : "r"(a[0]), "r"(a[1]), "r"(a[2]), "r"(a[3]), "r"(b[0]), "r"(b[1]));
}
__device__ __forceinline__ uint32_t pack2h(float a, float b) {
    __half2 t = __floats2half2_rn(a, b);
    return *(uint32_t*)&t;
}

// ---------------------------------------------------------------------------
// Static device scratch
// ---------------------------------------------------------------------------
__device__ __half g_Jh[64u * 1024u * 1024u];    // adj fp16
__device__ __half g_XT[64u * 512u * 1024u];     // x^T per batch [b][f][n]
__device__ __half g_W1T[1024u * 512u];          // W1^T [h1][f]
__device__ __half g_W2T[512u * 1024u];          // W2^T [h2][h1]
__device__ __half g_P1[65536u * 512u];          // adj@x  [n][f]
__device__ __half g_H1[65536u * 1024u];         // h1 [n][h1]
__device__ __half g_S2T[512u * 65536u];         // support2^T [h2][b*1024+n]
__device__ float  g_pool[64];

// ---------------------------------------------------------------------------
__global__ void __launch_bounds__(256)
convert_kernel(const float* __restrict__ src, __half* __restrict__ dst, size_t n4)
{
    size_t stride = (size_t)gridDim.x * blockDim.x;
    for (size_t i = (size_t)blockIdx.x * blockDim.x + threadIdx.x; i < n4; i += stride) {
        float4 v = ((const float4*)src)[i];
        uint2 o;
        o.x = pack2h(v.x, v.y);
        o.y = pack2h(v.z, v.w);
        ((uint2*)dst)[i] = o;
    }
}

// batched transpose-convert: x[b,n,f] fp32 -> xT[b,f,n] fp16 (32x32 smem tiles)
__global__ void __launch_bounds__(256)
xtrans_kernel(const float* __restrict__ src, __half* __restrict__ dst)
{
    __shared__ float tile[32][33];
    const int b = blockIdx.z;
    const int n0 = blockIdx.y * 32;
    const int f0 = blockIdx.x * 32;
    const int tx = threadIdx.x;
    const int ty = threadIdx.y;
    const float* s = src + ((size_t)b * 1024 + n0) * 512 + f0;
    #pragma unroll
    for (int i = ty; i < 32; i += 8) tile[i][tx] = s[(size_t)i * 512 + tx];
    __syncthreads();
    __half* d = dst + ((size_t)b * 512 + f0) * 1024 + n0;
    #pragma unroll
    for (int i = ty; i < 32; i += 8) d[(size_t)i * 1024 + tx] = __float2half(tile[tx][i]);
}

// transpose-convert small weights: src[R,C] fp32 -> dst[C,R] fp16
__global__ void __launch_bounds__(256)
tconvert_kernel(const float* __restrict__ src, __half* __restrict__ dst, int R, int C)
{
    int total = R * C;
    for (int idx = blockIdx.x * blockDim.x + threadIdx.x; idx < total;
         idx += gridDim.x * blockDim.x) {
        int r = idx / C, c = idx % C;
        dst[(size_t)c * R + r] = __float2half(src[idx]);
    }
}

// ---------------------------------------------------------------------------
// mma.sync fp16 GEMM: D[128,128] per CTA, 8 warps (2x4), warp tile 64x32.
// EPI: 0 = fp16 out; 1 = bias+ReLU fp16 out; 3 = bias+ReLU+masked pool.Wl.
// SWAP: blockIdx.x indexes M (keeps co-scheduled CTAs on the same B rows).
// ---------------------------------------------------------------------------
template <int EPI, bool SWAP>
__global__ void __launch_bounds__(256, 2)
mma_gemm(const __half* __restrict__ Ag, int lda, size_t strA,
         const __half* __restrict__ Bg, int ldb, size_t strB,
         const float* __restrict__ bias,
         __half* __restrict__ Ch, int ldc, size_t strC,
         const float* __restrict__ Wl, const int* __restrict__ length,
         float* __restrict__ pool,
         int nch)
{
    extern __shared__ char smem[];
    const int bz = blockIdx.z;
    const int m0 = (SWAP ? blockIdx.x : blockIdx.y) * BM;
    const int n0 = (SWAP ? blockIdx.y : blockIdx.x) * BN;

    int len = 0;
    if (EPI == 3) {
        len = length[bz];
        if (m0 >= len) return;
    }

    const uint32_t sb = smem_u32(smem);
    const int tid = threadIdx.x;
    const int wid = tid >> 5;
    const int l   = tid & 31;
    const int warp_m = wid & 1;    // 2 x 64 rows
    const int warp_n = wid >> 1;   // 4 x 32 cols

    const __half* pA = Ag + strA * bz;
    const __half* pB = Bg + strB * bz;

    const int ld_row = tid >> 3;
    const int ld_c16 = tid & 7;

    auto load_tiles = [&](int c, int st) {
        const int kbase = c * BK;
        const uint32_t sbase = sb + st * STG;
        #pragma unroll
        for (int it = 0; it < 4; it++) {
            const int row = ld_row + it * 32;
            cp16(sbase + SWZ((uint32_t)(row * 128 + ld_c16 * 16)),
                 pA + (size_t)(m0 + row) * lda + kbase + ld_c16 * 8);
        }
        #pragma unroll
        for (int it = 0; it < 4; it++) {
            const int row = ld_row + it * 32;
            cp16(sbase + A_BYTES + SWZ((uint32_t)(row * 128 + ld_c16 * 16)),
                 pB + (size_t)(n0 + row) * ldb + kbase + ld_c16 * 8);
        }
    };

    const int a_row_l = l & 15;
    const uint32_t a_koff = (uint32_t)((l >> 4) * 16);
    const int b_row_l = (l & 7) + ((l >> 4) * 8);
    const uint32_t b_koff = (uint32_t)(((l >> 3) & 1) * 16);

    uint32_t a_rb[4], b_rb[2];
    #pragma unroll
    for (int mi = 0; mi < 4; mi++)
        a_rb[mi] = (uint32_t)((warp_m * 64 + mi * 16 + a_row_l) * 128);
    #pragma unroll
    for (int nb = 0; nb < 2; nb++)
        b_rb[nb] = (uint32_t)((warp_n * 32 + nb * 16 + b_row_l) * 128);

    float acc[4][4][4];
    #pragma unroll
    for (int mi = 0; mi < 4; mi++)
        #pragma unroll
        for (int ni = 0; ni < 4; ni++)
            #pragma unroll
            for (int q = 0; q < 4; q++) acc[mi][ni][q] = 0.0f;

    load_tiles(0, 0);
    CP_COMMIT();
    if (1 < nch) { load_tiles(1, 1); CP_COMMIT(); }

    for (int c = 0; c < nch; c++) {
        if (c + 1 < nch) { CP_WAIT(1); } else { CP_WAIT(0); }
        __syncthreads();
        if (c + 2 < nch) {
            load_tiles(c + 2, (c + 2) % NSTG);
            CP_COMMIT();
        }

        const uint32_t sA = sb + (c % NSTG) * STG;
        const uint32_t sB = sA + A_BYTES;

        #pragma unroll
        for (int ks = 0; ks < 4; ks++) {
            const uint32_t kb = (uint32_t)(ks * 32);
            uint32_t Ah[4][4], Bh[2][4];
            #pragma unroll
            for (int mi = 0; mi < 4; mi++)
                ldsm4(Ah[mi], sA + SWZ(a_rb[mi] + kb + a_koff));
            #pragma unroll
            for (int nb = 0; nb < 2; nb++)
                ldsm4(Bh[nb], sB + SWZ(b_rb[nb] + kb + b_koff));
            #pragma unroll
            for (int mi = 0; mi < 4; mi++)
                #pragma unroll
                for (int ni = 0; ni < 4; ni++)
                    mma_fp16(acc[mi][ni], Ah[mi], &Bh[ni >> 1][(ni & 1) * 2]);
        }
        __syncthreads();
    }

    // ---- epilogue ----
    const int er = warp_m * 64 + (l >> 2);
    const int ec = warp_n * 32 + 2 * (l & 3);

    if (EPI <= 1) {
        #pragma unroll
        for (int mi = 0; mi < 4; mi++) {
            const int row = m0 + er + mi * 16;
            const size_t ro0 = strC * bz + (size_t)row * ldc;
            const size_t ro1 = ro0 + (size_t)8 * ldc;
            #pragma unroll
            for (int ni = 0; ni < 4; ni++) {
                const int col = n0 + ec + ni * 8;
                float v00 = acc[mi][ni][0], v01 = acc[mi][ni][1];
                float v10 = acc[mi][ni][2], v11 = acc[mi][ni][3];
                if (EPI == 1) {
                    const float2 bb = *(const float2*)(bias + col);
                    v00 = fmaxf(v00 + bb.x, 0.0f);
                    v01 = fmaxf(v01 + bb.y, 0.0f);
                    v10 = fmaxf(v10 + bb.x, 0.0f);
                    v11 = fmaxf(v11 + bb.y, 0.0f);
                }
                *(uint32_t*)(Ch + ro0 + col) = pack2h(v00, v01);
                *(uint32_t*)(Ch + ro1 + col) = pack2h(v10, v11);
            }
        }
    } else {
        // EPI==3: bias + ReLU + masked dot with Wl, reduce, atomicAdd per batch
        float part = 0.0f;
        #pragma unroll
        for (int mi = 0; mi < 4; mi++) {
            const int grow0 = m0 + er + mi * 16;
            const bool k0 = grow0 < len;
            const bool k1 = grow0 + 8 < len;
            #pragma unroll
            for (int ni = 0; ni < 4; ni++) {
                const int col = n0 + ec + ni * 8;
                const float2 bb = *(const float2*)(bias + col);
                const float2 wl = *(const float2*)(Wl + col);
                float v00 = fmaxf(acc[mi][ni][0] + bb.x, 0.0f);
                float v01 = fmaxf(acc[mi][ni][1] + bb.y, 0.0f);
                float v10 = fmaxf(acc[mi][ni][2] + bb.x, 0.0f);
                float v11 = fmaxf(acc[mi][ni][3] + bb.y, 0.0f);
                if (k0) part += v00 * wl.x + v01 * wl.y;
                if (k1) part += v10 * wl.x + v11 * wl.y;
            }
        }
        #pragma unroll
        for (int o = 16; o > 0; o >>= 1)
            part += __shfl_xor_sync(0xFFFFFFFFu, part, o);
        __syncthreads();
        float* red = (float*)smem;
        if (l == 0) red[wid] = part;
        __syncthreads();
        if (tid == 0) {
            float s = 0.0f;
            #pragma unroll
            for (int i = 0; i < 8; i++) s += red[i];
            atomicAdd(pool + bz, s);
        }
    }
}

// ---------------------------------------------------------------------------
__global__ void zero_pool_kernel(float* __restrict__ pool)
{
    pool[threadIdx.x] = 0.0f;
}

__global__ void final_kernel(const float* __restrict__ pool,
                             const int* __restrict__ length,
                             const float* __restrict__ bl,
                             float* __restrict__ out)
{
    const int b = threadIdx.x;
    out[b] = pool[b] / (float)length[b] + bl[0];
}

// ---------------------------------------------------------------------------
extern "C" void kernel_launch(void* const* d_in, const int* in_sizes, int n_in,
                              void* d_out, int out_size)
{
    const float* x      = (const float*)d_in[0];
    const float* adj    = (const float*)d_in[1];
    const int*   length = (const int*)  d_in[2];
    const float* W1     = (const float*)d_in[3];
    const float* b1     = (const float*)d_in[4];
    const float* W2     = (const float*)d_in[5];
    const float* b2     = (const float*)d_in[6];
    const float* Wl     = (const float*)d_in[7];
    const float* bl     = (const float*)d_in[8];
    float* out = (float*)d_out;

    __half *Jh, *XT, *W1T, *W2T, *P1, *H1, *S2T;
    float* pool;
    cudaGetSymbolAddress((void**)&Jh,  g_Jh);
    cudaGetSymbolAddress((void**)&XT,  g_XT);
    cudaGetSymbolAddress((void**)&W1T, g_W1T);
    cudaGetSymbolAddress((void**)&W2T, g_W2T);
    cudaGetSymbolAddress((void**)&P1,  g_P1);
    cudaGetSymbolAddress((void**)&H1,  g_H1);
    cudaGetSymbolAddress((void**)&S2T, g_S2T);
    cudaGetSymbolAddress((void**)&pool, g_pool);

    cudaFuncSetAttribute(mma_gemm<0, false>, cudaFuncAttributeMaxDynamicSharedMemorySize, SMEM_TOTAL);
    cudaFuncSetAttribute(mma_gemm<1, false>, cudaFuncAttributeMaxDynamicSharedMemorySize, SMEM_TOTAL);
    cudaFuncSetAttribute(mma_gemm<0, true>,  cudaFuncAttributeMaxDynamicSharedMemorySize, SMEM_TOTAL);
    cudaFuncSetAttribute(mma_gemm<3, false>, cudaFuncAttributeMaxDynamicSharedMemorySize, SMEM_TOTAL);

    // converts
    convert_kernel<<<8192, 256>>>(adj, Jh, (size_t)64 * 1024 * 1024 / 4);
    xtrans_kernel<<<dim3(16, 32, 64), dim3(32, 8)>>>(x, XT);
    tconvert_kernel<<<512, 256>>>(W1, W1T, 512, 1024);
    tconvert_kernel<<<512, 256>>>(W2, W2T, 1024, 512);

    // T1: P1[b] = adj[b] @ x[b]   (M=1024, N=512, K=1024) x64
    mma_gemm<0, false><<<dim3(4, 8, 64), 256, SMEM_TOTAL>>>(
        Jh, 1024, (size_t)1024 * 1024,
        XT, 1024, (size_t)512 * 1024,
        nullptr, P1, 512, (size_t)1024 * 512,
        nullptr, nullptr, nullptr, 1024 / BK);

    // T2: h1 = relu(P1 @ W1 + b1)  (M=65536, N=1024, K=512)
    mma_gemm<1, false><<<dim3(8, 512, 1), 256, SMEM_TOTAL>>>(
        P1, 512, 0,
        W1T, 512, 0,
        b1, H1, 1024, 0,
        nullptr, nullptr, nullptr, 512 / BK);

    // T3: S2^T = W2^T @ h1^T  (M=512, N=65536, K=1024), SWAP grid so the
    // co-scheduled M-blocks share each h1 row-group through L2.
    mma_gemm<0, true><<<dim3(4, 512, 1), 256, SMEM_TOTAL>>>(
        W2T, 1024, 0,
        H1, 1024, 0,
        nullptr, S2T, 65536, 0,
        nullptr, nullptr, nullptr, 1024 / BK);

    // T4: fused relu(adj[b]@S2[b]+b2) . Wl with row mask, row-block skip
    zero_pool_kernel<<<1, 64>>>(pool);
    mma_gemm<3, false><<<dim3(4, 8, 64), 256, SMEM_TOTAL>>>(
        Jh, 1024, (size_t)1024 * 1024,
        S2T, 65536, 1024,
        b2, nullptr, 0, 0,
        Wl, length, pool, 1024 / BK);

    final_kernel<<<1, 64>>>(pool, length, bl, out);

    (void)in_sizes; (void)n_in; (void)out_size;
}

// round 10
// speedup vs baseline: 12.1981x; 1.0587x over previous
#include <cuda_runtime.h>
#include <cuda_fp16.h>
#include <stdint.h>

// ===========================================================================
// GCN forward, fp16 mma.sync (fp32 accum), reassociated to minimize MACs:
//   T1: P1[b]   = adj[b] @ x[b]            (M=1024,N=512, K=1024) x64
//   T2: h1      = relu(P1 @ W1 + b1)       (M=65536,N=1024,K=512)
//   T3: S2^T    = W2^T @ h1^T              (M=512,N=65536,K=1024)  [SWAP grid]
//   T4: pool[b]+= mask.(relu(adj[b]@S2[b]+b2) . Wl)   (rows >= len skipped)
//   out[b] = pool[b]/len[b] + bl
// R8: vectorized smem-tiled transposes, redundant mainloop barrier removed,
// pool zeroing folded into the adj convert.
// ===========================================================================

#define BM 128
#define BN 128
#define BK 64                       // fp16 per chunk (=128B per row)
#define NSTG 3

#define A_BYTES (BM * 128)          // 16384
#define B_BYTES (BN * 128)          // 16384
#define STG     (A_BYTES + B_BYTES) // 32768
#define SMEM_TOTAL (NSTG * STG)     // 98304

#define SWZ(off) ((off) ^ (((off) >> 3) & 0x70))

__device__ __forceinline__ uint32_t smem_u32(const void* p) {
    uint32_t a;
    asm("{ .reg .u64 t; cvta.to.shared.u64 t, %1; cvt.u32.u64 %0, t; }" : "=r"(a) : "l"(p));
    return a;
}
__device__ __forceinline__ void cp16(uint32_t dst, const void* src) {
    asm volatile("cp.async.cg.shared.global [%0], [%1], 16;" :: "r"(dst), "l"(src));
}
#define CP_COMMIT() asm volatile("cp.async.commit_group;" ::: "memory")
#define CP_WAIT(n)  asm volatile("cp.async.wait_group %0;" :: "n"(n) : "memory")

__device__ __forceinline__ void ldsm4(uint32_t* r, uint32_t addr) {
    asm volatile("ldmatrix.sync.aligned.m8n8.x4.shared.b16 {%0,%1,%2,%3}, [%4];"
                 : "=r"(r[0]), "=r"(r[1]), "=r"(r[2]), "=r"(r[3]) : "r"(addr));
}
__device__ __forceinline__ void mma_fp16(float* d, const uint32_t* a, const uint32_t* b) {
    asm volatile("mma.sync.aligned.m16n8k16.row.col.f32.f16.f16.f32 "
                 "{%0,%1,%2,%3}, {%4,%5,%6,%7}, {%8,%9}, {%0,%1,%2,%3};"
                 : "+f"(d[0]), "+f"(d[1]), "+f"(d[2]), "+f"(d[3])
                 : "r"(a[0]), "r"(a[1]), "r"(a[2]), "r"(a[3]), "r"(b[0]), "r"(b[1]));
}
__device__ __forceinline__ uint32_t pack2h(float a, float b) {
    __half2 t = __floats2half2_rn(a, b);
    return *(uint32_t*)&t;
}

// ---------------------------------------------------------------------------
// Static device scratch
// ---------------------------------------------------------------------------
__device__ __half g_Jh[64u * 1024u * 1024u];    // adj fp16
__device__ __half g_XT[64u * 512u * 1024u];     // x^T per batch [b][f][n]
__device__ __half g_W1T[1024u * 512u];          // W1^T [h1][f]
__device__ __half g_W2T[512u * 1024u];          // W2^T [h2][h1]
__device__ __half g_P1[65536u * 512u];          // adj@x  [n][f]
__device__ __half g_H1[65536u * 1024u];         // h1 [n][h1]
__device__ __half g_S2T[512u * 65536u];         // support2^T [h2][b*1024+n]
__device__ float  g_pool[64];

// ---------------------------------------------------------------------------
// fp32 -> fp16 elementwise convert; block 0 also zeroes the pool accumulator.
// ---------------------------------------------------------------------------
__global__ void __launch_bounds__(256)
convert_kernel(const float* __restrict__ src, __half* __restrict__ dst, size_t n4,
               float* __restrict__ pool)
{
    if (pool != nullptr && blockIdx.x == 0 && threadIdx.x < 64)
        pool[threadIdx.x] = 0.0f;
    size_t stride = (size_t)gridDim.x * blockDim.x;
    for (size_t i = (size_t)blockIdx.x * blockDim.x + threadIdx.x; i < n4; i += stride) {
        float4 v = ((const float4*)src)[i];
        uint2 o;
        o.x = pack2h(v.x, v.y);
        o.y = pack2h(v.z, v.w);
        ((uint2*)dst)[i] = o;
    }
}

// ---------------------------------------------------------------------------
// Tiled transpose-convert: src[z][R][C] fp32 -> dst[z][C][R] fp16.
// 32x32 tiles; coalesced float loads, coalesced __half2 stores.
// ---------------------------------------------------------------------------
__global__ void __launch_bounds__(256)
trans_kernel(const float* __restrict__ src, __half* __restrict__ dst, int R, int C)
{
    __shared__ float tile[32][33];
    const size_t zoff = (size_t)blockIdx.z * R * C;
    const int r0 = blockIdx.y * 32;
    const int c0 = blockIdx.x * 32;
    const int tx = threadIdx.x & 31;
    const int ty = threadIdx.x >> 5;            // 0..7

    const float* s = src + zoff + (size_t)r0 * C + c0;
    #pragma unroll
    for (int i = ty; i < 32; i += 8) tile[i][tx] = s[(size_t)i * C + tx];
    __syncthreads();

    const int cc = threadIdx.x >> 4;            // 0..15
    const int rp = threadIdx.x & 15;            // 0..15 (pairs of rows)
    __half* d = dst + zoff;
    #pragma unroll
    for (int j = 0; j < 2; j++) {
        const int c = cc + j * 16;
        __half2 v = __floats2half2_rn(tile[2 * rp][c], tile[2 * rp + 1][c]);
        *(__half2*)(d + (size_t)(c0 + c) * R + r0 + 2 * rp) = v;
    }
}

// ---------------------------------------------------------------------------
// mma.sync fp16 GEMM: D[128,128] per CTA, 8 warps (2x4), warp tile 64x32.
// EPI: 0 = fp16 out; 1 = bias+ReLU fp16 out; 3 = bias+ReLU+masked pool.Wl.
// SWAP: blockIdx.x indexes M (keeps co-scheduled CTAs on the same B rows).
// ---------------------------------------------------------------------------
template <int EPI, bool SWAP>
__global__ void __launch_bounds__(256, 2)
mma_gemm(const __half* __restrict__ Ag, int lda, size_t strA,
         const __half* __restrict__ Bg, int ldb, size_t strB,
         const float* __restrict__ bias,
         __half* __restrict__ Ch, int ldc, size_t strC,
         const float* __restrict__ Wl, const int* __restrict__ length,
         float* __restrict__ pool,
         int nch)
{
    extern __shared__ char smem[];
    const int bz = blockIdx.z;
    const int m0 = (SWAP ? blockIdx.x : blockIdx.y) * BM;
    const int n0 = (SWAP ? blockIdx.y : blockIdx.x) * BN;

    int len = 0;
    if (EPI == 3) {
        len = length[bz];
        if (m0 >= len) return;
    }

    const uint32_t sb = smem_u32(smem);
    const int tid = threadIdx.x;
    const int wid = tid >> 5;
    const int l   = tid & 31;
    const int warp_m = wid & 1;    // 2 x 64 rows
    const int warp_n = wid >> 1;   // 4 x 32 cols

    const __half* pA = Ag + strA * bz;
    const __half* pB = Bg + strB * bz;

    const int ld_row = tid >> 3;
    const int ld_c16 = tid & 7;

    auto load_tiles = [&](int c, int st) {
        const int kbase = c * BK;
        const uint32_t sbase = sb + st * STG;
        #pragma unroll
        for (int it = 0; it < 4; it++) {
            const int row = ld_row + it * 32;
            cp16(sbase + SWZ((uint32_t)(row * 128 + ld_c16 * 16)),
                 pA + (size_t)(m0 + row) * lda + kbase + ld_c16 * 8);
        }
        #pragma unroll
        for (int it = 0; it < 4; it++) {
            const int row = ld_row + it * 32;
            cp16(sbase + A_BYTES + SWZ((uint32_t)(row * 128 + ld_c16 * 16)),
                 pB + (size_t)(n0 + row) * ldb + kbase + ld_c16 * 8);
        }
    };

    const int a_row_l = l & 15;
    const uint32_t a_koff = (uint32_t)((l >> 4) * 16);
    const int b_row_l = (l & 7) + ((l >> 4) * 8);
    const uint32_t b_koff = (uint32_t)(((l >> 3) & 1) * 16);

    uint32_t a_rb[4], b_rb[2];
    #pragma unroll
    for (int mi = 0; mi < 4; mi++)
        a_rb[mi] = (uint32_t)((warp_m * 64 + mi * 16 + a_row_l) * 128);
    #pragma unroll
    for (int nb = 0; nb < 2; nb++)
        b_rb[nb] = (uint32_t)((warp_n * 32 + nb * 16 + b_row_l) * 128);

    float acc[4][4][4];
    #pragma unroll
    for (int mi = 0; mi < 4; mi++)
        #pragma unroll
        for (int ni = 0; ni < 4; ni++)
            #pragma unroll
            for (int q = 0; q < 4; q++) acc[mi][ni][q] = 0.0f;

    load_tiles(0, 0);
    CP_COMMIT();
    if (1 < nch) { load_tiles(1, 1); CP_COMMIT(); }

    for (int c = 0; c < nch; c++) {
        if (c + 1 < nch) { CP_WAIT(1); } else { CP_WAIT(0); }
        __syncthreads();
        // Safe without a trailing barrier: stage (c+2)%3 == (c-1)%3, and every
        // warp consumed stage c-1 before it could reach the barrier above.
        if (c + 2 < nch) {
            load_tiles(c + 2, (c + 2) % NSTG);
            CP_COMMIT();
        }

        const uint32_t sA = sb + (c % NSTG) * STG;
        const uint32_t sB = sA + A_BYTES;

        #pragma unroll
        for (int ks = 0; ks < 4; ks++) {
            const uint32_t kb = (uint32_t)(ks * 32);
            uint32_t Ah[4][4], Bh[2][4];
            #pragma unroll
            for (int mi = 0; mi < 4; mi++)
                ldsm4(Ah[mi], sA + SWZ(a_rb[mi] + kb + a_koff));
            #pragma unroll
            for (int nb = 0; nb < 2; nb++)
                ldsm4(Bh[nb], sB + SWZ(b_rb[nb] + kb + b_koff));
            #pragma unroll
            for (int mi = 0; mi < 4; mi++)
                #pragma unroll
                for (int ni = 0; ni < 4; ni++)
                    mma_fp16(acc[mi][ni], Ah[mi], &Bh[ni >> 1][(ni & 1) * 2]);
        }
    }

    // ---- epilogue ----
    const int er = warp_m * 64 + (l >> 2);
    const int ec = warp_n * 32 + 2 * (l & 3);

    if (EPI <= 1) {
        #pragma unroll
        for (int mi = 0; mi < 4; mi++) {
            const int row = m0 + er + mi * 16;
            const size_t ro0 = strC * bz + (size_t)row * ldc;
            const size_t ro1 = ro0 + (size_t)8 * ldc;
            #pragma unroll
            for (int ni = 0; ni < 4; ni++) {
                const int col = n0 + ec + ni * 8;
                float v00 = acc[mi][ni][0], v01 = acc[mi][ni][1];
                float v10 = acc[mi][ni][2], v11 = acc[mi][ni][3];
                if (EPI == 1) {
                    const float2 bb = *(const float2*)(bias + col);
                    v00 = fmaxf(v00 + bb.x, 0.0f);
                    v01 = fmaxf(v01 + bb.y, 0.0f);
                    v10 = fmaxf(v10 + bb.x, 0.0f);
                    v11 = fmaxf(v11 + bb.y, 0.0f);
                }
                *(uint32_t*)(Ch + ro0 + col) = pack2h(v00, v01);
                *(uint32_t*)(Ch + ro1 + col) = pack2h(v10, v11);
            }
        }
    } else {
        // EPI==3: bias + ReLU + masked dot with Wl, reduce, atomicAdd per batch
        float part = 0.0f;
        #pragma unroll
        for (int mi = 0; mi < 4; mi++) {
            const int grow0 = m0 + er + mi * 16;
            const bool k0 = grow0 < len;
            const bool k1 = grow0 + 8 < len;
            #pragma unroll
            for (int ni = 0; ni < 4; ni++) {
                const int col = n0 + ec + ni * 8;
                const float2 bb = *(const float2*)(bias + col);
                const float2 wl = *(const float2*)(Wl + col);
                float v00 = fmaxf(acc[mi][ni][0] + bb.x, 0.0f);
                float v01 = fmaxf(acc[mi][ni][1] + bb.y, 0.0f);
                float v10 = fmaxf(acc[mi][ni][2] + bb.x, 0.0f);
                float v11 = fmaxf(acc[mi][ni][3] + bb.y, 0.0f);
                if (k0) part += v00 * wl.x + v01 * wl.y;
                if (k1) part += v10 * wl.x + v11 * wl.y;
            }
        }
        #pragma unroll
        for (int o = 16; o > 0; o >>= 1)
            part += __shfl_xor_sync(0xFFFFFFFFu, part, o);
        __syncthreads();
        float* red = (float*)smem;
        if (l == 0) red[wid] = part;
        __syncthreads();
        if (tid == 0) {
            float s = 0.0f;
            #pragma unroll
            for (int i = 0; i < 8; i++) s += red[i];
            atomicAdd(pool + bz, s);
        }
    }
}

// ---------------------------------------------------------------------------
__global__ void final_kernel(const float* __restrict__ pool,
                             const int* __restrict__ length,
                             const float* __restrict__ bl,
                             float* __restrict__ out)
{
    const int b = threadIdx.x;
    out[b] = pool[b] / (float)length[b] + bl[0];
}

// ---------------------------------------------------------------------------
extern "C" void kernel_launch(void* const* d_in, const int* in_sizes, int n_in,
                              void* d_out, int out_size)
{
    const float* x      = (const float*)d_in[0];
    const float* adj    = (const float*)d_in[1];
    const int*   length = (const int*)  d_in[2];
    const float* W1     = (const float*)d_in[3];
    const float* b1     = (const float*)d_in[4];
    const float* W2     = (const float*)d_in[5];
    const float* b2     = (const float*)d_in[6];
    const float* Wl     = (const float*)d_in[7];
    const float* bl     = (const float*)d_in[8];
    float* out = (float*)d_out;

    __half *Jh, *XT, *W1T, *W2T, *P1, *H1, *S2T;
    float* pool;
    cudaGetSymbolAddress((void**)&Jh,  g_Jh);
    cudaGetSymbolAddress((void**)&XT,  g_XT);
    cudaGetSymbolAddress((void**)&W1T, g_W1T);
    cudaGetSymbolAddress((void**)&W2T, g_W2T);
    cudaGetSymbolAddress((void**)&P1,  g_P1);
    cudaGetSymbolAddress((void**)&H1,  g_H1);
    cudaGetSymbolAddress((void**)&S2T, g_S2T);
    cudaGetSymbolAddress((void**)&pool, g_pool);

    cudaFuncSetAttribute(mma_gemm<0, false>, cudaFuncAttributeMaxDynamicSharedMemorySize, SMEM_TOTAL);
    cudaFuncSetAttribute(mma_gemm<1, false>, cudaFuncAttributeMaxDynamicSharedMemorySize, SMEM_TOTAL);
    cudaFuncSetAttribute(mma_gemm<0, true>,  cudaFuncAttributeMaxDynamicSharedMemorySize, SMEM_TOTAL);
    cudaFuncSetAttribute(mma_gemm<3, false>, cudaFuncAttributeMaxDynamicSharedMemorySize, SMEM_TOTAL);

    // converts (adj convert also zeroes the pool accumulator)
    convert_kernel<<<8192, 256>>>(adj, Jh, (size_t)64 * 1024 * 1024 / 4, pool);
    trans_kernel<<<dim3(16, 32, 64), 256>>>(x,  XT,  1024, 512);   // x^T per batch
    trans_kernel<<<dim3(32, 16, 1),  256>>>(W1, W1T, 512, 1024);   // W1^T
    trans_kernel<<<dim3(16, 32, 1),  256>>>(W2, W2T, 1024, 512);   // W2^T

    // T1: P1[b] = adj[b] @ x[b]   (M=1024, N=512, K=1024) x64
    mma_gemm<0, false><<<dim3(4, 8, 64), 256, SMEM_TOTAL>>>(
        Jh, 1024, (size_t)1024 * 1024,
        XT, 1024, (size_t)512 * 1024,
        nullptr, P1, 512, (size_t)1024 * 512,
        nullptr, nullptr, nullptr, 1024 / BK);

    // T2: h1 = relu(P1 @ W1 + b1)  (M=65536, N=1024, K=512)
    mma_gemm<1, false><<<dim3(8, 512, 1), 256, SMEM_TOTAL>>>(
        P1, 512, 0,
        W1T, 512, 0,
        b1, H1, 1024, 0,
        nullptr, nullptr, nullptr, 512 / BK);

    // T3: S2^T = W2^T @ h1^T  (M=512, N=65536, K=1024), SWAP grid so the
    // co-scheduled M-blocks share each h1 row-group through L2.
    mma_gemm<0, true><<<dim3(4, 512, 1), 256, SMEM_TOTAL>>>(
        W2T, 1024, 0,
        H1, 1024, 0,
        nullptr, S2T, 65536, 0,
        nullptr, nullptr, nullptr, 1024 / BK);

    // T4: fused relu(adj[b]@S2[b]+b2) . Wl with row mask, row-block skip
    mma_gemm<3, false><<<dim3(4, 8, 64), 256, SMEM_TOTAL>>>(
        Jh, 1024, (size_t)1024 * 1024,
        S2T, 65536, 1024,
        b2, nullptr, 0, 0,
        Wl, length, pool, 1024 / BK);

    final_kernel<<<1, 64>>>(pool, length, bl, out);

    (void)in_sizes; (void)n_in; (void)out_size;
}